// round 2
// baseline (speedup 1.0000x reference)
#include <cuda_runtime.h>

// Problem constants
#define Bb 4
#define Cc 256
#define VC 128
#define NT 4096   // H*W = 64*64

// Scratch for Q/K/V in [b][n][d] layout (d contiguous)
__device__ float g_Q[Bb * NT * VC];
__device__ float g_K[Bb * NT * VC];
__device__ float g_V[Bb * NT * VC];

// ---------------------------------------------------------------------------
// QKV projection: Out[b][n][d] = sum_c W[d][c] * x[b][c][n]
// GEMM tiles: 64 n  x 64 d, K-chunks of 16. 256 threads, 4x4 micro-tile.
// grid = (NT/64, 6, Bb); blockIdx.y selects (weight, d-half).
// ---------------------------------------------------------------------------
__global__ __launch_bounds__(256) void qkv_proj_kernel(
    const float* __restrict__ x,
    const float* __restrict__ Wq,
    const float* __restrict__ Wk,
    const float* __restrict__ Wv)
{
    __shared__ float Xs[16][65];   // [c][n]
    __shared__ float Ws[16][65];   // [c][d]

    const int b    = blockIdx.z;
    const int n0   = blockIdx.x * 64;
    const int slab = blockIdx.y;           // 0..5
    const int wi   = slab >> 1;            // 0=Q 1=K 2=V
    const int d0   = (slab & 1) * 64;

    const float* W   = (wi == 0) ? Wq : (wi == 1) ? Wk : Wv;
    float*       Out = (wi == 0) ? g_Q : (wi == 1) ? g_K : g_V;

    const int tid = threadIdx.x;
    const int tn  = tid & 15;   // n group
    const int td  = tid >> 4;   // d group

    float acc[4][4] = {};

    const float* xb = x + (size_t)b * Cc * NT;

    for (int c0 = 0; c0 < Cc; c0 += 16) {
        // X tile: coalesced along n
        #pragma unroll
        for (int idx = tid; idx < 16 * 64; idx += 256) {
            int c = idx >> 6, n = idx & 63;
            Xs[c][n] = xb[(size_t)(c0 + c) * NT + n0 + n];
        }
        // W tile: Ws[c][d] = W[(d0+d)*Cc + c0+c]
        #pragma unroll
        for (int idx = tid; idx < 16 * 64; idx += 256) {
            int d = idx >> 4, c = idx & 15;
            Ws[c][d] = W[(size_t)(d0 + d) * Cc + c0 + c];
        }
        __syncthreads();

        #pragma unroll
        for (int c = 0; c < 16; c++) {
            float xa[4], wb[4];
            #pragma unroll
            for (int i = 0; i < 4; i++) xa[i] = Xs[c][tn * 4 + i];
            #pragma unroll
            for (int j = 0; j < 4; j++) wb[j] = Ws[c][td * 4 + j];
            #pragma unroll
            for (int i = 0; i < 4; i++)
                #pragma unroll
                for (int j = 0; j < 4; j++)
                    acc[i][j] += xa[i] * wb[j];
        }
        __syncthreads();
    }

    #pragma unroll
    for (int i = 0; i < 4; i++) {
        float4 v = make_float4(acc[i][0], acc[i][1], acc[i][2], acc[i][3]);
        *(float4*)&Out[((size_t)b * NT + n0 + tn * 4 + i) * VC + d0 + td * 4] = v;
    }
}

// ---------------------------------------------------------------------------
// Flash attention, fp32 SIMT.
// Per block: BM=128 queries of one batch; loop over 64 key-tiles of BN=64.
//   S stage : per-thread 4q x 8k (q = lane*4 via float4 from transposed-Q smem,
//             k = warp*8 broadcast from K smem) -> Pt[k][q]
//   softmax : threads 0..127 each own one q row (m,l live in registers)
//   PV stage: per-thread 8q x 8d (P broadcast, V via float4)
// grid = (NT/BM, Bb), 256 threads.
// ---------------------------------------------------------------------------
#define BM 128
#define BN 64
#define DD 128
#define QT_STR 132   // Qt[d][q] stride (mult of 4 for float4 reads)
#define KV_STR 132   // Ks/Vs[k][d] stride
#define PT_STR 132   // Pt[k][q] stride

struct SmemFA {
    float Qt[DD * QT_STR];   // [d][q]; reused as Ot[d][q] for the epilogue
    float Ks[BN * KV_STR];   // [k][d]
    float Vs[BN * KV_STR];   // [k][d]
    float Pt[BN * PT_STR];   // [k][q] scores -> probabilities
    float sc[BM];            // per-row rescale factor this tile
    float lsum[BM];          // final denominators
};

extern __shared__ float fa_smem_raw[];

__global__ __launch_bounds__(256, 1) void fa_kernel(float* __restrict__ out)
{
    SmemFA* s = (SmemFA*)fa_smem_raw;

    const int b   = blockIdx.y;
    const int n0  = blockIdx.x * BM;
    const int tid = threadIdx.x;
    const int lane = tid & 31;
    const int warp = tid >> 5;

    const float* Qg = g_Q + ((size_t)b * NT + n0) * VC;
    const float* Kg = g_K + (size_t)b * NT * VC;
    const float* Vg = g_V + (size_t)b * NT * VC;

    // Load Q transposed: Qt[d][q]
    for (int idx = tid; idx < BM * 32; idx += 256) {
        int q = idx >> 5, c4 = idx & 31;
        float4 v = *(const float4*)&Qg[(size_t)q * VC + c4 * 4];
        s->Qt[(c4 * 4 + 0) * QT_STR + q] = v.x;
        s->Qt[(c4 * 4 + 1) * QT_STR + q] = v.y;
        s->Qt[(c4 * 4 + 2) * QT_STR + q] = v.z;
        s->Qt[(c4 * 4 + 3) * QT_STR + q] = v.w;
    }

    // PV accumulator mapping
    const int qp0 = (tid >> 4) * 8;   // 0..120
    const int dp0 = (tid & 15) * 8;   // 0..120
    float o[8][8];
    #pragma unroll
    for (int i = 0; i < 8; i++)
        #pragma unroll
        for (int j = 0; j < 8; j++) o[i][j] = 0.f;

    // S-stage mapping
    const int qs0 = lane * 4;   // 0..124
    const int ks0 = warp * 8;   // 0..56

    // Row stats live in registers of threads 0..127 (row = tid)
    float m_r = -1e30f, l_r = 0.f;

    for (int t = 0; t < NT / BN; t++) {
        const int k0g = t * BN;
        __syncthreads();   // protect Ks/Vs/Pt from previous iteration

        // Load K,V tiles (coalesced float4)
        for (int idx = tid; idx < BN * 32; idx += 256) {
            int k = idx >> 5, c4 = idx & 31;
            *(float4*)&s->Ks[k * KV_STR + c4 * 4] =
                *(const float4*)&Kg[(size_t)(k0g + k) * VC + c4 * 4];
            *(float4*)&s->Vs[k * KV_STR + c4 * 4] =
                *(const float4*)&Vg[(size_t)(k0g + k) * VC + c4 * 4];
        }
        __syncthreads();

        // ---- S = Q . K^T  (raw logits, no 1/sqrt(d): matches reference) ----
        float acc[4][8];
        #pragma unroll
        for (int i = 0; i < 4; i++)
            #pragma unroll
            for (int j = 0; j < 8; j++) acc[i][j] = 0.f;

        #pragma unroll 2
        for (int d = 0; d < DD; d++) {
            float4 qa = *(const float4*)&s->Qt[d * QT_STR + qs0];
            float kb[8];
            #pragma unroll
            for (int j = 0; j < 8; j++) kb[j] = s->Ks[(ks0 + j) * KV_STR + d];
            #pragma unroll
            for (int j = 0; j < 8; j++) {
                acc[0][j] += qa.x * kb[j];
                acc[1][j] += qa.y * kb[j];
                acc[2][j] += qa.z * kb[j];
                acc[3][j] += qa.w * kb[j];
            }
        }
        #pragma unroll
        for (int j = 0; j < 8; j++) {
            *(float4*)&s->Pt[(ks0 + j) * PT_STR + qs0] =
                make_float4(acc[0][j], acc[1][j], acc[2][j], acc[3][j]);
        }
        __syncthreads();

        // ---- online softmax: one thread per q row ----
        if (tid < BM) {
            const int q = tid;
            float mx0 = m_r, mx1 = -1e30f, mx2 = -1e30f, mx3 = -1e30f;
            #pragma unroll 4
            for (int k = 0; k < BN; k += 4) {
                mx0 = fmaxf(mx0, s->Pt[(k + 0) * PT_STR + q]);
                mx1 = fmaxf(mx1, s->Pt[(k + 1) * PT_STR + q]);
                mx2 = fmaxf(mx2, s->Pt[(k + 2) * PT_STR + q]);
                mx3 = fmaxf(mx3, s->Pt[(k + 3) * PT_STR + q]);
            }
            float mx = fmaxf(fmaxf(mx0, mx1), fmaxf(mx2, mx3));
            float scale = __expf(m_r - mx);
            float s0 = 0.f, s1 = 0.f, s2 = 0.f, s3 = 0.f;
            #pragma unroll 4
            for (int k = 0; k < BN; k += 4) {
                float p0 = __expf(s->Pt[(k + 0) * PT_STR + q] - mx);
                float p1 = __expf(s->Pt[(k + 1) * PT_STR + q] - mx);
                float p2 = __expf(s->Pt[(k + 2) * PT_STR + q] - mx);
                float p3 = __expf(s->Pt[(k + 3) * PT_STR + q] - mx);
                s->Pt[(k + 0) * PT_STR + q] = p0;
                s->Pt[(k + 1) * PT_STR + q] = p1;
                s->Pt[(k + 2) * PT_STR + q] = p2;
                s->Pt[(k + 3) * PT_STR + q] = p3;
                s0 += p0; s1 += p1; s2 += p2; s3 += p3;
            }
            l_r = l_r * scale + (s0 + s1) + (s2 + s3);
            m_r = mx;
            s->sc[q] = scale;
        }
        __syncthreads();

        // ---- rescale O, accumulate P.V ----
        float scl[8];
        #pragma unroll
        for (int i = 0; i < 8; i++) scl[i] = s->sc[qp0 + i];
        #pragma unroll
        for (int i = 0; i < 8; i++)
            #pragma unroll
            for (int j = 0; j < 8; j++) o[i][j] *= scl[i];

        #pragma unroll 2
        for (int k = 0; k < BN; k++) {
            float4 v0 = *(const float4*)&s->Vs[k * KV_STR + dp0];
            float4 v1 = *(const float4*)&s->Vs[k * KV_STR + dp0 + 4];
            float pa[8];
            #pragma unroll
            for (int i = 0; i < 8; i++) pa[i] = s->Pt[k * PT_STR + qp0 + i];
            #pragma unroll
            for (int i = 0; i < 8; i++) {
                o[i][0] += pa[i] * v0.x;
                o[i][1] += pa[i] * v0.y;
                o[i][2] += pa[i] * v0.z;
                o[i][3] += pa[i] * v0.w;
                o[i][4] += pa[i] * v1.x;
                o[i][5] += pa[i] * v1.y;
                o[i][6] += pa[i] * v1.z;
                o[i][7] += pa[i] * v1.w;
            }
        }
    }

    // Publish denominators
    __syncthreads();
    if (tid < BM) s->lsum[tid] = l_r;
    __syncthreads();

    float linv[8];
    #pragma unroll
    for (int i = 0; i < 8; i++) linv[i] = 1.0f / s->lsum[qp0 + i];

    // Transpose O through smem (reuse Qt as Ot[d][q]) for coalesced writes
    #pragma unroll
    for (int i = 0; i < 8; i++)
        #pragma unroll
        for (int j = 0; j < 8; j++)
            s->Qt[(dp0 + j) * QT_STR + (qp0 + i)] = o[i][j] * linv[i];
    __syncthreads();

    float* outb = out + (size_t)b * VC * NT;
    for (int idx = tid; idx < VC * BM; idx += 256) {
        int d = idx >> 7;       // /128
        int q = idx & 127;
        outb[(size_t)d * NT + n0 + q] = s->Qt[d * QT_STR + q];
    }
}

// ---------------------------------------------------------------------------
extern "C" void kernel_launch(void* const* d_in, const int* in_sizes, int n_in,
                              void* d_out, int out_size)
{
    const float* x  = (const float*)d_in[0];
    const float* Wq = (const float*)d_in[1];
    const float* Wk = (const float*)d_in[2];
    const float* Wv = (const float*)d_in[3];
    float* out = (float*)d_out;

    // QKV projection
    dim3 g1(NT / 64, 6, Bb);
    qkv_proj_kernel<<<g1, 256>>>(x, Wq, Wk, Wv);

    // Flash attention (dynamic smem > 48 KB)
    cudaFuncSetAttribute(fa_kernel, cudaFuncAttributeMaxDynamicSharedMemorySize,
                         (int)sizeof(SmemFA));
    dim3 g2(NT / BM, Bb);
    fa_kernel<<<g2, 256, sizeof(SmemFA)>>>(out);
}

// round 4
// speedup vs baseline: 2.8819x; 2.8819x over previous
#include <cuda_runtime.h>
#include <cuda_bf16.h>
#include <cstdint>

// ---------------------------------------------------------------------------
// Problem constants
// ---------------------------------------------------------------------------
#define Bb 4
#define Cc 256
#define VC 128
#define NT 4096          // H*W
#define BM 128           // queries per CTA
#define BN 64            // keys per tile
#define NTILES (NT / BN) // 64

// Scratch: split-bf16 Q/K in [b][n][d], V in [b][d][n] (transposed)
__device__ __nv_bfloat16 g_Qhi[Bb * NT * VC];
__device__ __nv_bfloat16 g_Qlo[Bb * NT * VC];
__device__ __nv_bfloat16 g_Khi[Bb * NT * VC];
__device__ __nv_bfloat16 g_Klo[Bb * NT * VC];
__device__ __nv_bfloat16 g_Vhi[Bb * VC * NT];
__device__ __nv_bfloat16 g_Vlo[Bb * VC * NT];

// ---------------------------------------------------------------------------
// helpers
// ---------------------------------------------------------------------------
__device__ __forceinline__ uint32_t smem_u32(const void* p) {
    uint32_t a;
    asm("{ .reg .u64 t; cvta.to.shared.u64 t, %1; cvt.u32.u64 %0, t; }"
        : "=r"(a) : "l"(p));
    return a;
}

#define CP_ASYNC16(dst, src) \
    asm volatile("cp.async.cg.shared.global [%0], [%1], 16;" \
                 :: "r"(dst), "l"(src) : "memory")
#define CP_COMMIT() asm volatile("cp.async.commit_group;" ::: "memory")
#define CP_WAIT1()  asm volatile("cp.async.wait_group 1;" ::: "memory")

__device__ __forceinline__ void ldsm_x4(uint32_t addr, uint32_t& r0, uint32_t& r1,
                                        uint32_t& r2, uint32_t& r3) {
    asm volatile("ldmatrix.sync.aligned.m8n8.x4.shared.b16 {%0,%1,%2,%3}, [%4];"
                 : "=r"(r0), "=r"(r1), "=r"(r2), "=r"(r3) : "r"(addr));
}

__device__ __forceinline__ void mma_bf16(float* c, const uint32_t a[4],
                                         uint32_t b0, uint32_t b1) {
    asm volatile(
        "mma.sync.aligned.m16n8k16.row.col.f32.bf16.bf16.f32 "
        "{%0,%1,%2,%3}, {%4,%5,%6,%7}, {%8,%9}, {%0,%1,%2,%3};"
        : "+f"(c[0]), "+f"(c[1]), "+f"(c[2]), "+f"(c[3])
        : "r"(a[0]), "r"(a[1]), "r"(a[2]), "r"(a[3]), "r"(b0), "r"(b1));
}

__device__ __forceinline__ void split_bf(float v, __nv_bfloat16& h, __nv_bfloat16& l) {
    h = __float2bfloat16_rn(v);
    l = __float2bfloat16_rn(v - __bfloat162float(h));
}
__device__ __forceinline__ uint32_t pk(__nv_bfloat16 a, __nv_bfloat16 b) {
    __nv_bfloat162 t = __halves2bfloat162(a, b);
    uint32_t u;
    *reinterpret_cast<__nv_bfloat162*>(&u) = t;
    return u;
}
__device__ __forceinline__ uint32_t pk_hi(float a, float b) {
    return pk(__float2bfloat16_rn(a), __float2bfloat16_rn(b));
}

// swizzled byte offsets: 256B rows (Q/K, 16 chunks of 16B), 128B rows (V, 8 chunks)
__device__ __forceinline__ uint32_t swz_q(int row, int ch) {
    return (uint32_t)(row * 256 + ((ch ^ (row & 7)) << 4));
}
__device__ __forceinline__ uint32_t swz_v(int row, int ch) {
    return (uint32_t)(row * 128 + ((ch ^ (row & 7)) << 4));
}

// ---------------------------------------------------------------------------
// QKV projection -> split-bf16. Q,K: [b][n][d]; V: [b][d][n].
// ---------------------------------------------------------------------------
__global__ __launch_bounds__(256) void qkv_proj_kernel(
    const float* __restrict__ x,
    const float* __restrict__ Wq,
    const float* __restrict__ Wk,
    const float* __restrict__ Wv)
{
    __shared__ float Xs[16][65];
    __shared__ float Ws[16][65];

    const int b    = blockIdx.z;
    const int n0   = blockIdx.x * 64;
    const int slab = blockIdx.y;
    const int wi   = slab >> 1;            // 0=Q 1=K 2=V
    const int d0   = (slab & 1) * 64;

    const float* W = (wi == 0) ? Wq : (wi == 1) ? Wk : Wv;

    const int tid = threadIdx.x;
    const int tn  = tid & 15;
    const int td  = tid >> 4;

    float acc[4][4] = {};
    const float* xb = x + (size_t)b * Cc * NT;

    for (int c0 = 0; c0 < Cc; c0 += 16) {
        #pragma unroll
        for (int idx = tid; idx < 16 * 64; idx += 256) {
            int c = idx >> 6, n = idx & 63;
            Xs[c][n] = xb[(size_t)(c0 + c) * NT + n0 + n];
        }
        #pragma unroll
        for (int idx = tid; idx < 16 * 64; idx += 256) {
            int d = idx >> 4, c = idx & 15;
            Ws[c][d] = W[(size_t)(d0 + d) * Cc + c0 + c];
        }
        __syncthreads();
        #pragma unroll
        for (int c = 0; c < 16; c++) {
            float xa[4], wb[4];
            #pragma unroll
            for (int i = 0; i < 4; i++) xa[i] = Xs[c][tn * 4 + i];
            #pragma unroll
            for (int j = 0; j < 4; j++) wb[j] = Ws[c][td * 4 + j];
            #pragma unroll
            for (int i = 0; i < 4; i++)
                #pragma unroll
                for (int j = 0; j < 4; j++)
                    acc[i][j] += xa[i] * wb[j];
        }
        __syncthreads();
    }

    if (wi < 2) {
        __nv_bfloat16* Bh = (wi == 0) ? g_Qhi : g_Khi;
        __nv_bfloat16* Bl = (wi == 0) ? g_Qlo : g_Klo;
        #pragma unroll
        for (int i = 0; i < 4; i++) {
            __nv_bfloat16 h[4], l[4];
            #pragma unroll
            for (int j = 0; j < 4; j++) split_bf(acc[i][j], h[j], l[j]);
            size_t off = ((size_t)b * NT + n0 + tn * 4 + i) * VC + d0 + td * 4;
            *(uint2*)(Bh + off) = make_uint2(pk(h[0], h[1]), pk(h[2], h[3]));
            *(uint2*)(Bl + off) = make_uint2(pk(l[0], l[1]), pk(l[2], l[3]));
        }
    } else {
        #pragma unroll
        for (int j = 0; j < 4; j++) {
            __nv_bfloat16 h[4], l[4];
            #pragma unroll
            for (int i = 0; i < 4; i++) split_bf(acc[i][j], h[i], l[i]);
            size_t off = ((size_t)b * VC + d0 + td * 4 + j) * NT + n0 + tn * 4;
            *(uint2*)(g_Vhi + off) = make_uint2(pk(h[0], h[1]), pk(h[2], h[3]));
            *(uint2*)(g_Vlo + off) = make_uint2(pk(l[0], l[1]), pk(l[2], l[3]));
        }
    }
}

// ---------------------------------------------------------------------------
// Flash attention via mma.sync (bf16, 3-pass split), no-max softmax.
// smem (dynamic, 192KB):
//   Qhi 0..32K, Qlo 32K..64K        (128 rows x 256B, swizzled)
//   Khi [2][16K] at 64K, Klo [2][16K] at 96K   (64 rows x 256B each buf)
//   Vhi [2][16K] at 128K, Vlo [2][16K] at 160K (128 rows x 128B each buf)
//   epilogue Ot (float[128*132]) aliases offset 64K
// ---------------------------------------------------------------------------
#define QHI_OFF 0
#define QLO_OFF 32768
#define KHI_OFF 65536
#define KLO_OFF 98304
#define VHI_OFF 131072
#define VLO_OFF 163840
#define S_TOTAL 196608
#define KBUF 16384

extern __shared__ char fa_sm[];

__device__ __forceinline__ void load_kv(uint32_t sbase, int b, int t, int buf, int tid)
{
    const int k0 = t * BN;
    // K: 64 rows x 16 chunks, hi+lo
    #pragma unroll
    for (int comp = 0; comp < 2; comp++) {
        const __nv_bfloat16* src = comp ? g_Klo : g_Khi;
        uint32_t dst = sbase + (comp ? KLO_OFF : KHI_OFF) + buf * KBUF;
        #pragma unroll
        for (int i = tid; i < 64 * 16; i += 256) {
            int row = i >> 4, ch = i & 15;
            const char* g = (const char*)(src + ((size_t)b * NT + k0 + row) * VC) + ch * 16;
            CP_ASYNC16(dst + swz_q(row, ch), g);
        }
    }
    // V: 128 d-rows x 8 chunks (64 keys), hi+lo
    #pragma unroll
    for (int comp = 0; comp < 2; comp++) {
        const __nv_bfloat16* src = comp ? g_Vlo : g_Vhi;
        uint32_t dst = sbase + (comp ? VLO_OFF : VHI_OFF) + buf * KBUF;
        #pragma unroll
        for (int i = tid; i < 128 * 8; i += 256) {
            int row = i >> 3, ch = i & 7;
            const char* g = (const char*)(src + ((size_t)b * VC + row) * NT + k0) + ch * 16;
            CP_ASYNC16(dst + swz_v(row, ch), g);
        }
    }
}

__global__ __launch_bounds__(256, 1) void fa_kernel(float* __restrict__ out)
{
    const int tid  = threadIdx.x;
    const int w    = tid >> 5;
    const int lane = tid & 31;
    const int b    = blockIdx.y;
    const int n0   = blockIdx.x * BM;
    const int q0   = w * 16;                 // warp's query rows

    char* sm = fa_sm;
    const uint32_t sbase = smem_u32(sm);

    // ---- stage Q (hi/lo) into swizzled smem via cp.async ----
    #pragma unroll
    for (int comp = 0; comp < 2; comp++) {
        const __nv_bfloat16* src = comp ? g_Qlo : g_Qhi;
        uint32_t dst = sbase + (comp ? QLO_OFF : QHI_OFF);
        #pragma unroll
        for (int i = tid; i < 128 * 16; i += 256) {
            int row = i >> 4, ch = i & 15;
            const char* g = (const char*)(src + ((size_t)b * NT + n0 + row) * VC) + ch * 16;
            CP_ASYNC16(dst + swz_q(row, ch), g);
        }
    }
    // prefetch tile 0
    load_kv(sbase, b, 0, 0, tid);
    CP_COMMIT();

    float O[16][4];
    #pragma unroll
    for (int i = 0; i < 16; i++)
        #pragma unroll
        for (int j = 0; j < 4; j++) O[i][j] = 0.f;
    float rs0 = 0.f, rs1 = 0.f;

    // ldmatrix lane address components
    const int a_row = q0 + (lane & 15);            // A frags (Q): rows
    const int a_ch  = (lane >> 4);                 // +0/+1 16B chunk
    const int b_row = (lane & 7) + ((lane >> 4) << 3);   // B frags: row within 16
    const int b_ch  = ((lane >> 3) & 1);

    #pragma unroll 1
    for (int t = 0; t < NTILES; t++) {
        const int buf = t & 1;
        if (t + 1 < NTILES) load_kv(sbase, b, t + 1, buf ^ 1, tid);
        CP_COMMIT();
        CP_WAIT1();
        __syncthreads();

        const uint32_t kh_base = sbase + KHI_OFF + buf * KBUF;
        const uint32_t kl_base = sbase + KLO_OFF + buf * KBUF;
        const uint32_t vh_base = sbase + VHI_OFF + buf * KBUF;
        const uint32_t vl_base = sbase + VLO_OFF + buf * KBUF;

        // ---- S = Q K^T (3-pass split) ----
        float C[8][4];
        #pragma unroll
        for (int i = 0; i < 8; i++)
            #pragma unroll
            for (int j = 0; j < 4; j++) C[i][j] = 0.f;

        #pragma unroll
        for (int kc = 0; kc < 8; kc++) {
            uint32_t aqh[4], aql[4];
            ldsm_x4(sbase + QHI_OFF + swz_q(a_row, 2 * kc + a_ch),
                    aqh[0], aqh[1], aqh[2], aqh[3]);
            ldsm_x4(sbase + QLO_OFF + swz_q(a_row, 2 * kc + a_ch),
                    aql[0], aql[1], aql[2], aql[3]);
            #pragma unroll
            for (int ntp = 0; ntp < 4; ntp++) {
                uint32_t bh0, bh1, bh2, bh3, bl0, bl1, bl2, bl3;
                ldsm_x4(kh_base + swz_q(ntp * 16 + b_row, 2 * kc + b_ch),
                        bh0, bh1, bh2, bh3);
                ldsm_x4(kl_base + swz_q(ntp * 16 + b_row, 2 * kc + b_ch),
                        bl0, bl1, bl2, bl3);
                mma_bf16(C[2 * ntp],     aqh, bh0, bh1);
                mma_bf16(C[2 * ntp + 1], aqh, bh2, bh3);
                mma_bf16(C[2 * ntp],     aqh, bl0, bl1);
                mma_bf16(C[2 * ntp + 1], aqh, bl2, bl3);
                mma_bf16(C[2 * ntp],     aql, bh0, bh1);
                mma_bf16(C[2 * ntp + 1], aql, bh2, bh3);
            }
        }

        // ---- softmax (no max subtraction) + split-bf16 P ----
        uint32_t Phi[8][2], Plo[8][2];
        #pragma unroll
        for (int nt = 0; nt < 8; nt++) {
            float p0 = __expf(C[nt][0]);
            float p1 = __expf(C[nt][1]);
            float p2 = __expf(C[nt][2]);
            float p3 = __expf(C[nt][3]);
            rs0 += p0 + p1;
            rs1 += p2 + p3;
            Phi[nt][0] = pk_hi(p0, p1);
            Phi[nt][1] = pk_hi(p2, p3);
            float q0f = p0 - __bfloat162float(__float2bfloat16_rn(p0));
            float q1f = p1 - __bfloat162float(__float2bfloat16_rn(p1));
            float q2f = p2 - __bfloat162float(__float2bfloat16_rn(p2));
            float q3f = p3 - __bfloat162float(__float2bfloat16_rn(p3));
            Plo[nt][0] = pk_hi(q0f, q1f);
            Plo[nt][1] = pk_hi(q2f, q3f);
        }

        // ---- O += P V (3-pass split) ----
        #pragma unroll
        for (int kc = 0; kc < 4; kc++) {
            uint32_t aph[4] = {Phi[2 * kc][0], Phi[2 * kc][1],
                               Phi[2 * kc + 1][0], Phi[2 * kc + 1][1]};
            uint32_t apl[4] = {Plo[2 * kc][0], Plo[2 * kc][1],
                               Plo[2 * kc + 1][0], Plo[2 * kc + 1][1]};
            #pragma unroll
            for (int ntp = 0; ntp < 8; ntp++) {
                uint32_t bh0, bh1, bh2, bh3, bl0, bl1, bl2, bl3;
                ldsm_x4(vh_base + swz_v(ntp * 16 + b_row, 2 * kc + b_ch),
                        bh0, bh1, bh2, bh3);
                ldsm_x4(vl_base + swz_v(ntp * 16 + b_row, 2 * kc + b_ch),
                        bl0, bl1, bl2, bl3);
                mma_bf16(O[2 * ntp],     aph, bh0, bh1);
                mma_bf16(O[2 * ntp + 1], aph, bh2, bh3);
                mma_bf16(O[2 * ntp],     aph, bl0, bl1);
                mma_bf16(O[2 * ntp + 1], aph, bl2, bl3);
                mma_bf16(O[2 * ntp],     apl, bh0, bh1);
                mma_bf16(O[2 * ntp + 1], apl, bh2, bh3);
            }
        }
        __syncthreads();   // all warps done with buf before it is refilled
    }

    // ---- finalize: quad-reduce rowsums, normalize, transpose, store ----
    rs0 += __shfl_xor_sync(0xffffffffu, rs0, 1);
    rs0 += __shfl_xor_sync(0xffffffffu, rs0, 2);
    rs1 += __shfl_xor_sync(0xffffffffu, rs1, 1);
    rs1 += __shfl_xor_sync(0xffffffffu, rs1, 2);
    const float inv0 = 1.0f / rs0;
    const float inv1 = 1.0f / rs1;

    __syncthreads();
    float* Ot = (float*)(sm + KHI_OFF);   // 128x132 floats, fits in K/V region
    const int r  = lane >> 2;
    const int cc = (lane & 3) * 2;
    #pragma unroll
    for (int nt = 0; nt < 16; nt++) {
        int d = nt * 8 + cc;
        Ot[d * 132 + q0 + r]           = O[nt][0] * inv0;
        Ot[(d + 1) * 132 + q0 + r]     = O[nt][1] * inv0;
        Ot[d * 132 + q0 + r + 8]       = O[nt][2] * inv1;
        Ot[(d + 1) * 132 + q0 + r + 8] = O[nt][3] * inv1;
    }
    __syncthreads();

    float* outb = out + (size_t)b * VC * NT;
    #pragma unroll
    for (int i = tid; i < VC * BM; i += 256) {
        int d = i >> 7, q = i & 127;
        outb[(size_t)d * NT + n0 + q] = Ot[d * 132 + q];
    }
}

// ---------------------------------------------------------------------------
extern "C" void kernel_launch(void* const* d_in, const int* in_sizes, int n_in,
                              void* d_out, int out_size)
{
    const float* x  = (const float*)d_in[0];
    const float* Wq = (const float*)d_in[1];
    const float* Wk = (const float*)d_in[2];
    const float* Wv = (const float*)d_in[3];
    float* out = (float*)d_out;

    dim3 g1(NT / 64, 6, Bb);
    qkv_proj_kernel<<<g1, 256>>>(x, Wq, Wk, Wv);

    cudaFuncSetAttribute(fa_kernel, cudaFuncAttributeMaxDynamicSharedMemorySize, S_TOTAL);
    dim3 g2(NT / BM, Bb);
    fa_kernel<<<g2, 256, S_TOTAL>>>(out);
}

// round 6
// speedup vs baseline: 3.8168x; 1.3244x over previous
#include <cuda_runtime.h>
#include <cuda_bf16.h>
#include <cuda_fp16.h>
#include <cstdint>

// ---------------------------------------------------------------------------
// Problem constants
// ---------------------------------------------------------------------------
#define Bb 4
#define Cc 256
#define VC 128
#define NT 4096          // H*W
#define BM 128           // queries per CTA
#define BN 64            // keys per tile
#define NTILES (NT / BN) // 64
#define LOG2E 1.4426950408889634f

// Scratch: split-bf16 Q/K in [b][n][d] (Q pre-scaled by log2e), V fp16 [b][d][n]
__device__ __nv_bfloat16 g_Qhi[Bb * NT * VC];
__device__ __nv_bfloat16 g_Qlo[Bb * NT * VC];
__device__ __nv_bfloat16 g_Khi[Bb * NT * VC];
__device__ __nv_bfloat16 g_Klo[Bb * NT * VC];
__device__ __half        g_V  [Bb * VC * NT];

// ---------------------------------------------------------------------------
// helpers
// ---------------------------------------------------------------------------
__device__ __forceinline__ uint32_t smem_u32(const void* p) {
    uint32_t a;
    asm("{ .reg .u64 t; cvta.to.shared.u64 t, %1; cvt.u32.u64 %0, t; }"
        : "=r"(a) : "l"(p));
    return a;
}

#define CP_ASYNC16(dst, src) \
    asm volatile("cp.async.cg.shared.global [%0], [%1], 16;" \
                 :: "r"(dst), "l"(src) : "memory")
#define CP_COMMIT() asm volatile("cp.async.commit_group;" ::: "memory")
#define CP_WAIT1()  asm volatile("cp.async.wait_group 1;" ::: "memory")

__device__ __forceinline__ void ldsm_x4(uint32_t addr, uint32_t& r0, uint32_t& r1,
                                        uint32_t& r2, uint32_t& r3) {
    asm volatile("ldmatrix.sync.aligned.m8n8.x4.shared.b16 {%0,%1,%2,%3}, [%4];"
                 : "=r"(r0), "=r"(r1), "=r"(r2), "=r"(r3) : "r"(addr));
}

__device__ __forceinline__ void mma_bf16(float* c, const uint32_t a[4],
                                         uint32_t b0, uint32_t b1) {
    asm volatile(
        "mma.sync.aligned.m16n8k16.row.col.f32.bf16.bf16.f32 "
        "{%0,%1,%2,%3}, {%4,%5,%6,%7}, {%8,%9}, {%0,%1,%2,%3};"
        : "+f"(c[0]), "+f"(c[1]), "+f"(c[2]), "+f"(c[3])
        : "r"(a[0]), "r"(a[1]), "r"(a[2]), "r"(a[3]), "r"(b0), "r"(b1));
}
__device__ __forceinline__ void mma_f16(float* c, const uint32_t a[4],
                                        uint32_t b0, uint32_t b1) {
    asm volatile(
        "mma.sync.aligned.m16n8k16.row.col.f32.f16.f16.f32 "
        "{%0,%1,%2,%3}, {%4,%5,%6,%7}, {%8,%9}, {%0,%1,%2,%3};"
        : "+f"(c[0]), "+f"(c[1]), "+f"(c[2]), "+f"(c[3])
        : "r"(a[0]), "r"(a[1]), "r"(a[2]), "r"(a[3]), "r"(b0), "r"(b1));
}

__device__ __forceinline__ void split_bf(float v, __nv_bfloat16& h, __nv_bfloat16& l) {
    h = __float2bfloat16_rn(v);
    l = __float2bfloat16_rn(v - __bfloat162float(h));
}
__device__ __forceinline__ uint32_t pk(__nv_bfloat16 a, __nv_bfloat16 b) {
    __nv_bfloat162 t = __halves2bfloat162(a, b);
    uint32_t u;
    *reinterpret_cast<__nv_bfloat162*>(&u) = t;
    return u;
}
__device__ __forceinline__ uint32_t pkh(__half a, __half b) {
    __half2 t = __halves2half2(a, b);
    uint32_t u;
    *reinterpret_cast<__half2*>(&u) = t;
    return u;
}

// swizzled byte offsets: 256B rows (Q/K tiles, 16 chunks of 16B), 128B rows (8 chunks)
__device__ __forceinline__ uint32_t swz_q(int row, int ch) {
    return (uint32_t)(row * 256 + ((ch ^ (row & 7)) << 4));
}
__device__ __forceinline__ uint32_t swz_v(int row, int ch) {
    return (uint32_t)(row * 128 + ((ch ^ (row & 7)) << 4));
}

// ---------------------------------------------------------------------------
// Tensor-core QKV projection (split-bf16, 3-pass).
// out[n][d] = sum_c x[b][c][n] * W[d][c];   M=128 n, N=128 d, K=256 (4 chunks of 64)
// grid (NT/128, 3, Bb), 256 threads. Emits Q*log2e / K split-bf16 [b][n][d],
// V single-fp16 transposed [b][d][n].
// ---------------------------------------------------------------------------
#define PA_HI 0
#define PA_LO 16384
#define PB_HI 32768
#define PB_LO 49152
#define P_XS  65536               // float[64][132] staging (33792 B)
#define P_SMEM (65536 + 33792)

extern __shared__ char proj_sm[];

__global__ __launch_bounds__(256, 1) void proj_mma_kernel(
    const float* __restrict__ x,
    const float* __restrict__ Wq,
    const float* __restrict__ Wk,
    const float* __restrict__ Wv)
{
    const int b  = blockIdx.z;
    const int wi = blockIdx.y;            // 0=Q 1=K 2=V
    const int n0 = blockIdx.x * 128;
    const float* W = (wi == 0) ? Wq : (wi == 1) ? Wk : Wv;

    const int tid  = threadIdx.x;
    const int w    = tid >> 5;
    const int lane = tid & 31;
    const int q0   = w * 16;

    char* psm = proj_sm;
    const uint32_t sb = smem_u32(psm);
    float* Xs = (float*)(psm + P_XS);

    const int a_row = q0 + (lane & 15);
    const int a_c16 = lane >> 4;
    const int b_row = (lane & 7) + ((lane >> 4) << 3);
    const int b_ch  = (lane >> 3) & 1;

    float C[16][4];
    #pragma unroll
    for (int i = 0; i < 16; i++)
        #pragma unroll
        for (int j = 0; j < 4; j++) C[i][j] = 0.f;

    for (int kc = 0; kc < 4; kc++) {
        const int c0 = kc * 64;
        __syncthreads();
        // stage x chunk [64 c][128 n] coalesced
        const float* xb = x + ((size_t)b * Cc + c0) * NT + n0;
        #pragma unroll
        for (int i = tid; i < 64 * 32; i += 256) {
            int c = i >> 5, n4 = i & 31;
            float4 v = *(const float4*)(xb + (size_t)c * NT + n4 * 4);
            float* dst = &Xs[c * 132 + n4 * 4];
            dst[0] = v.x; dst[1] = v.y; dst[2] = v.z; dst[3] = v.w;
        }
        __syncthreads();

        // build A (transpose+split) and B (split) swizzled bf16 tiles
        {
            const int nn = tid & 127, cg = tid >> 7;
            #pragma unroll
            for (int oc = cg; oc < 8; oc += 2) {
                float f[8];
                #pragma unroll
                for (int j = 0; j < 8; j++) f[j] = Xs[(oc * 8 + j) * 132 + nn];
                uint32_t hw[4], lw[4];
                #pragma unroll
                for (int j = 0; j < 4; j++) {
                    __nv_bfloat16 h0, l0, h1, l1;
                    split_bf(f[2 * j], h0, l0);
                    split_bf(f[2 * j + 1], h1, l1);
                    hw[j] = pk(h0, h1); lw[j] = pk(l0, l1);
                }
                *(uint4*)(psm + PA_HI + swz_v(nn, oc)) = make_uint4(hw[0], hw[1], hw[2], hw[3]);
                *(uint4*)(psm + PA_LO + swz_v(nn, oc)) = make_uint4(lw[0], lw[1], lw[2], lw[3]);

                const float* wrow = W + (size_t)nn * Cc + c0 + oc * 8;
                float4 wa = *(const float4*)wrow;
                float4 wb = *(const float4*)(wrow + 4);
                float g[8] = {wa.x, wa.y, wa.z, wa.w, wb.x, wb.y, wb.z, wb.w};
                #pragma unroll
                for (int j = 0; j < 4; j++) {
                    __nv_bfloat16 h0, l0, h1, l1;
                    split_bf(g[2 * j], h0, l0);
                    split_bf(g[2 * j + 1], h1, l1);
                    hw[j] = pk(h0, h1); lw[j] = pk(l0, l1);
                }
                *(uint4*)(psm + PB_HI + swz_v(nn, oc)) = make_uint4(hw[0], hw[1], hw[2], hw[3]);
                *(uint4*)(psm + PB_LO + swz_v(nn, oc)) = make_uint4(lw[0], lw[1], lw[2], lw[3]);
            }
        }
        __syncthreads();

        // mma: 4 k16 x 8 B-ldsm x 6 mma (3 passes x 2 n8)
        #pragma unroll
        for (int kk = 0; kk < 4; kk++) {
            uint32_t ah[4], al[4];
            ldsm_x4(sb + PA_HI + swz_v(a_row, 2 * kk + a_c16), ah[0], ah[1], ah[2], ah[3]);
            ldsm_x4(sb + PA_LO + swz_v(a_row, 2 * kk + a_c16), al[0], al[1], al[2], al[3]);
            #pragma unroll
            for (int nt = 0; nt < 8; nt++) {
                uint32_t bh0, bh1, bh2, bh3, bl0, bl1, bl2, bl3;
                ldsm_x4(sb + PB_HI + swz_v(nt * 16 + b_row, 2 * kk + b_ch), bh0, bh1, bh2, bh3);
                ldsm_x4(sb + PB_LO + swz_v(nt * 16 + b_row, 2 * kk + b_ch), bl0, bl1, bl2, bl3);
                mma_bf16(C[2 * nt],     ah, bh0, bh1);
                mma_bf16(C[2 * nt + 1], ah, bh2, bh3);
                mma_bf16(C[2 * nt],     ah, bl0, bl1);
                mma_bf16(C[2 * nt + 1], ah, bl2, bl3);
                mma_bf16(C[2 * nt],     al, bh0, bh1);
                mma_bf16(C[2 * nt + 1], al, bh2, bh3);
            }
        }
    }

    // ---- epilogue ----
    const int r  = lane >> 2;
    const int cq = (lane & 3) * 2;

    if (wi < 2) {
        __nv_bfloat16* Bh = (wi == 0) ? g_Qhi : g_Khi;
        __nv_bfloat16* Bl = (wi == 0) ? g_Qlo : g_Klo;
        const float sc = (wi == 0) ? LOG2E : 1.0f;
        #pragma unroll
        for (int nt = 0; nt < 16; nt++) {
            int d = nt * 8 + cq;
            __nv_bfloat16 h0, l0, h1, l1;
            split_bf(C[nt][0] * sc, h0, l0);
            split_bf(C[nt][1] * sc, h1, l1);
            size_t o0 = ((size_t)b * NT + n0 + q0 + r) * VC + d;
            *(uint32_t*)(Bh + o0) = pk(h0, h1);
            *(uint32_t*)(Bl + o0) = pk(l0, l1);
            split_bf(C[nt][2] * sc, h0, l0);
            split_bf(C[nt][3] * sc, h1, l1);
            size_t o1 = o0 + (size_t)8 * VC;
            *(uint32_t*)(Bh + o1) = pk(h0, h1);
            *(uint32_t*)(Bl + o1) = pk(l0, l1);
        }
    } else {
        // V: transpose through smem (reuse Xs region), store fp16 [b][d][n]
        float* Vt = Xs;   // 64 x 132 floats
        #pragma unroll
        for (int h = 0; h < 2; h++) {
            __syncthreads();
            #pragma unroll
            for (int nt = h * 8; nt < h * 8 + 8; nt++) {
                int dl = nt * 8 + cq - h * 64;
                Vt[dl * 132 + q0 + r]             = C[nt][0];
                Vt[(dl + 1) * 132 + q0 + r]       = C[nt][1];
                Vt[dl * 132 + q0 + r + 8]         = C[nt][2];
                Vt[(dl + 1) * 132 + q0 + r + 8]   = C[nt][3];
            }
            __syncthreads();
            #pragma unroll
            for (int i = tid; i < 64 * 64; i += 256) {
                int dd = i >> 6, n2 = i & 63;
                __half2 hv = __floats2half2_rn(Vt[dd * 132 + n2 * 2],
                                               Vt[dd * 132 + n2 * 2 + 1]);
                *(__half2*)(g_V + ((size_t)b * VC + h * 64 + dd) * NT + n0 + n2 * 2) = hv;
            }
        }
    }
}

// ---------------------------------------------------------------------------
// Flash attention: bf16 3-pass S + fp16 2-pass PV, online-max softmax (base-2).
// smem (160KB): Qhi 0, Qlo 32K, Khi[2] 64K, Klo[2] 96K, V[2] 128K..160K
// ---------------------------------------------------------------------------
#define QHI_OFF 0
#define QLO_OFF 32768
#define KHI_OFF 65536
#define KLO_OFF 98304
#define V_OFF   131072
#define KBUF 16384
#define S_TOTAL 163840

extern __shared__ char fa_sm[];

__device__ __forceinline__ void load_kv(uint32_t sbase, int b, int t, int buf, int tid)
{
    const int k0 = t * BN;
    #pragma unroll
    for (int comp = 0; comp < 2; comp++) {
        const __nv_bfloat16* src = comp ? g_Klo : g_Khi;
        uint32_t dst = sbase + (comp ? KLO_OFF : KHI_OFF) + buf * KBUF;
        #pragma unroll
        for (int i = tid; i < 64 * 16; i += 256) {
            int row = i >> 4, ch = i & 15;
            const char* g = (const char*)(src + ((size_t)b * NT + k0 + row) * VC) + ch * 16;
            CP_ASYNC16(dst + swz_q(row, ch), g);
        }
    }
    {
        uint32_t dst = sbase + V_OFF + buf * KBUF;
        #pragma unroll
        for (int i = tid; i < 128 * 8; i += 256) {
            int row = i >> 3, ch = i & 7;
            const char* g = (const char*)(g_V + ((size_t)b * VC + row) * NT + k0) + ch * 16;
            CP_ASYNC16(dst + swz_v(row, ch), g);
        }
    }
}

__global__ __launch_bounds__(256, 1) void fa_kernel(float* __restrict__ out)
{
    const int tid  = threadIdx.x;
    const int w    = tid >> 5;
    const int lane = tid & 31;
    const int b    = blockIdx.y;
    const int n0   = blockIdx.x * BM;
    const int q0   = w * 16;

    char* sm = fa_sm;
    const uint32_t sbase = smem_u32(sm);

    // stage Q (hi/lo)
    #pragma unroll
    for (int comp = 0; comp < 2; comp++) {
        const __nv_bfloat16* src = comp ? g_Qlo : g_Qhi;
        uint32_t dst = sbase + (comp ? QLO_OFF : QHI_OFF);
        #pragma unroll
        for (int i = tid; i < 128 * 16; i += 256) {
            int row = i >> 4, ch = i & 15;
            const char* g = (const char*)(src + ((size_t)b * NT + n0 + row) * VC) + ch * 16;
            CP_ASYNC16(dst + swz_q(row, ch), g);
        }
    }
    load_kv(sbase, b, 0, 0, tid);
    CP_COMMIT();

    float O[16][4];
    #pragma unroll
    for (int i = 0; i < 16; i++)
        #pragma unroll
        for (int j = 0; j < 4; j++) O[i][j] = 0.f;
    float rs0 = 0.f, rs1 = 0.f;
    float M0 = -1e30f, M1 = -1e30f;

    const int a_row = q0 + (lane & 15);
    const int a_ch  = (lane >> 4);
    const int b_row = (lane & 7) + ((lane >> 4) << 3);
    const int b_ch  = ((lane >> 3) & 1);

    #pragma unroll 1
    for (int t = 0; t < NTILES; t++) {
        const int buf = t & 1;
        if (t + 1 < NTILES) load_kv(sbase, b, t + 1, buf ^ 1, tid);
        CP_COMMIT();
        CP_WAIT1();
        __syncthreads();

        const uint32_t kh_base = sbase + KHI_OFF + buf * KBUF;
        const uint32_t kl_base = sbase + KLO_OFF + buf * KBUF;
        const uint32_t v_base  = sbase + V_OFF   + buf * KBUF;

        // ---- S = Q K^T (bf16 3-pass), logits in base-2 (Q pre-scaled) ----
        float C[8][4];
        #pragma unroll
        for (int i = 0; i < 8; i++)
            #pragma unroll
            for (int j = 0; j < 4; j++) C[i][j] = 0.f;

        #pragma unroll
        for (int kc = 0; kc < 8; kc++) {
            uint32_t aqh[4], aql[4];
            ldsm_x4(sbase + QHI_OFF + swz_q(a_row, 2 * kc + a_ch),
                    aqh[0], aqh[1], aqh[2], aqh[3]);
            ldsm_x4(sbase + QLO_OFF + swz_q(a_row, 2 * kc + a_ch),
                    aql[0], aql[1], aql[2], aql[3]);
            #pragma unroll
            for (int ntp = 0; ntp < 4; ntp++) {
                uint32_t bh0, bh1, bh2, bh3, bl0, bl1, bl2, bl3;
                ldsm_x4(kh_base + swz_q(ntp * 16 + b_row, 2 * kc + b_ch),
                        bh0, bh1, bh2, bh3);
                ldsm_x4(kl_base + swz_q(ntp * 16 + b_row, 2 * kc + b_ch),
                        bl0, bl1, bl2, bl3);
                mma_bf16(C[2 * ntp],     aqh, bh0, bh1);
                mma_bf16(C[2 * ntp + 1], aqh, bh2, bh3);
                mma_bf16(C[2 * ntp],     aqh, bl0, bl1);
                mma_bf16(C[2 * ntp + 1], aqh, bl2, bl3);
                mma_bf16(C[2 * ntp],     aql, bh0, bh1);
                mma_bf16(C[2 * ntp + 1], aql, bh2, bh3);
            }
        }

        // ---- online softmax (base-2), P -> fp16 hi/lo ----
        float tm0 = -1e30f, tm1 = -1e30f;
        #pragma unroll
        for (int nt = 0; nt < 8; nt++) {
            tm0 = fmaxf(tm0, fmaxf(C[nt][0], C[nt][1]));
            tm1 = fmaxf(tm1, fmaxf(C[nt][2], C[nt][3]));
        }
        tm0 = fmaxf(tm0, __shfl_xor_sync(0xffffffffu, tm0, 1));
        tm0 = fmaxf(tm0, __shfl_xor_sync(0xffffffffu, tm0, 2));
        tm1 = fmaxf(tm1, __shfl_xor_sync(0xffffffffu, tm1, 1));
        tm1 = fmaxf(tm1, __shfl_xor_sync(0xffffffffu, tm1, 2));
        const float M0n = fmaxf(M0, tm0);
        const float M1n = fmaxf(M1, tm1);
        const float s0 = exp2f(M0 - M0n);
        const float s1 = exp2f(M1 - M1n);
        M0 = M0n; M1 = M1n;
        rs0 *= s0; rs1 *= s1;

        uint32_t Phi[8][2], Plo[8][2];
        #pragma unroll
        for (int nt = 0; nt < 8; nt++) {
            float p0 = exp2f(C[nt][0] - M0);
            float p1 = exp2f(C[nt][1] - M0);
            float p2 = exp2f(C[nt][2] - M1);
            float p3 = exp2f(C[nt][3] - M1);
            rs0 += p0 + p1;
            rs1 += p2 + p3;
            __half h0 = __float2half_rn(p0), h1 = __float2half_rn(p1);
            __half h2 = __float2half_rn(p2), h3 = __float2half_rn(p3);
            Phi[nt][0] = pkh(h0, h1);
            Phi[nt][1] = pkh(h2, h3);
            Plo[nt][0] = pkh(__float2half_rn(p0 - __half2float(h0)),
                             __float2half_rn(p1 - __half2float(h1)));
            Plo[nt][1] = pkh(__float2half_rn(p2 - __half2float(h2)),
                             __float2half_rn(p3 - __half2float(h3)));
        }

        // rescale O
        #pragma unroll
        for (int nt = 0; nt < 16; nt++) {
            O[nt][0] *= s0; O[nt][1] *= s0;
            O[nt][2] *= s1; O[nt][3] *= s1;
        }

        // ---- O += P V (fp16 2-pass: Phi*V + Plo*V) ----
        #pragma unroll
        for (int kc = 0; kc < 4; kc++) {
            uint32_t aph[4] = {Phi[2 * kc][0], Phi[2 * kc][1],
                               Phi[2 * kc + 1][0], Phi[2 * kc + 1][1]};
            uint32_t apl[4] = {Plo[2 * kc][0], Plo[2 * kc][1],
                               Plo[2 * kc + 1][0], Plo[2 * kc + 1][1]};
            #pragma unroll
            for (int ntp = 0; ntp < 8; ntp++) {
                uint32_t v0, v1, v2, v3;
                ldsm_x4(v_base + swz_v(ntp * 16 + b_row, 2 * kc + b_ch),
                        v0, v1, v2, v3);
                mma_f16(O[2 * ntp],     aph, v0, v1);
                mma_f16(O[2 * ntp + 1], aph, v2, v3);
                mma_f16(O[2 * ntp],     apl, v0, v1);
                mma_f16(O[2 * ntp + 1], apl, v2, v3);
            }
        }
        __syncthreads();
    }

    // ---- finalize ----
    rs0 += __shfl_xor_sync(0xffffffffu, rs0, 1);
    rs0 += __shfl_xor_sync(0xffffffffu, rs0, 2);
    rs1 += __shfl_xor_sync(0xffffffffu, rs1, 1);
    rs1 += __shfl_xor_sync(0xffffffffu, rs1, 2);
    const float inv0 = 1.0f / rs0;
    const float inv1 = 1.0f / rs1;

    __syncthreads();
    float* Ot = (float*)(sm + KHI_OFF);   // 128x132 floats fits in K/V region
    const int r  = lane >> 2;
    const int cc = (lane & 3) * 2;
    #pragma unroll
    for (int nt = 0; nt < 16; nt++) {
        int d = nt * 8 + cc;
        Ot[d * 132 + q0 + r]           = O[nt][0] * inv0;
        Ot[(d + 1) * 132 + q0 + r]     = O[nt][1] * inv0;
        Ot[d * 132 + q0 + r + 8]       = O[nt][2] * inv1;
        Ot[(d + 1) * 132 + q0 + r + 8] = O[nt][3] * inv1;
    }
    __syncthreads();

    float* outb = out + (size_t)b * VC * NT;
    #pragma unroll
    for (int i = tid; i < VC * BM; i += 256) {
        int d = i >> 7, q = i & 127;
        outb[(size_t)d * NT + n0 + q] = Ot[d * 132 + q];
    }
}

// ---------------------------------------------------------------------------
extern "C" void kernel_launch(void* const* d_in, const int* in_sizes, int n_in,
                              void* d_out, int out_size)
{
    const float* x  = (const float*)d_in[0];
    const float* Wq = (const float*)d_in[1];
    const float* Wk = (const float*)d_in[2];
    const float* Wv = (const float*)d_in[3];
    float* out = (float*)d_out;

    cudaFuncSetAttribute(proj_mma_kernel, cudaFuncAttributeMaxDynamicSharedMemorySize, P_SMEM);
    dim3 g1(NT / 128, 3, Bb);
    proj_mma_kernel<<<g1, 256, P_SMEM>>>(x, Wq, Wk, Wv);

    cudaFuncSetAttribute(fa_kernel, cudaFuncAttributeMaxDynamicSharedMemorySize, S_TOTAL);
    dim3 g2(NT / BM, Bb);
    fa_kernel<<<g2, 256, S_TOTAL>>>(out);
}

// round 7
// speedup vs baseline: 4.1667x; 1.0917x over previous
#include <cuda_runtime.h>
#include <cuda_bf16.h>
#include <cuda_fp16.h>
#include <cstdint>

// ---------------------------------------------------------------------------
// Problem constants
// ---------------------------------------------------------------------------
#define Bb 4
#define Cc 256
#define VC 128
#define NT 4096          // H*W
#define BM 128           // queries per CTA
#define BN 64            // keys per tile
#define NTILES (NT / BN) // 64
#define LOG2E 1.4426950408889634f

// Scratch
__device__ __nv_bfloat16 g_xhi[Bb * NT * Cc];   // x split, [b][n][c]
__device__ __nv_bfloat16 g_xlo[Bb * NT * Cc];
__device__ __nv_bfloat16 g_Qhi[Bb * NT * VC];   // Q*log2e split, [b][n][d]
__device__ __nv_bfloat16 g_Qlo[Bb * NT * VC];
__device__ __nv_bfloat16 g_Khi[Bb * NT * VC];
__device__ __nv_bfloat16 g_Klo[Bb * NT * VC];
__device__ __half        g_V  [Bb * VC * NT];   // V fp16, [b][d][n]

// ---------------------------------------------------------------------------
// helpers
// ---------------------------------------------------------------------------
__device__ __forceinline__ uint32_t smem_u32(const void* p) {
    uint32_t a;
    asm("{ .reg .u64 t; cvta.to.shared.u64 t, %1; cvt.u32.u64 %0, t; }"
        : "=r"(a) : "l"(p));
    return a;
}

#define CP_ASYNC16(dst, src) \
    asm volatile("cp.async.cg.shared.global [%0], [%1], 16;" \
                 :: "r"(dst), "l"(src) : "memory")
#define CP_COMMIT() asm volatile("cp.async.commit_group;" ::: "memory")
#define CP_WAIT1()  asm volatile("cp.async.wait_group 1;" ::: "memory")

__device__ __forceinline__ void ldsm_x4(uint32_t addr, uint32_t& r0, uint32_t& r1,
                                        uint32_t& r2, uint32_t& r3) {
    asm volatile("ldmatrix.sync.aligned.m8n8.x4.shared.b16 {%0,%1,%2,%3}, [%4];"
                 : "=r"(r0), "=r"(r1), "=r"(r2), "=r"(r3) : "r"(addr));
}

__device__ __forceinline__ void mma_bf16(float* c, const uint32_t a[4],
                                         uint32_t b0, uint32_t b1) {
    asm volatile(
        "mma.sync.aligned.m16n8k16.row.col.f32.bf16.bf16.f32 "
        "{%0,%1,%2,%3}, {%4,%5,%6,%7}, {%8,%9}, {%0,%1,%2,%3};"
        : "+f"(c[0]), "+f"(c[1]), "+f"(c[2]), "+f"(c[3])
        : "r"(a[0]), "r"(a[1]), "r"(a[2]), "r"(a[3]), "r"(b0), "r"(b1));
}
__device__ __forceinline__ void mma_f16(float* c, const uint32_t a[4],
                                        uint32_t b0, uint32_t b1) {
    asm volatile(
        "mma.sync.aligned.m16n8k16.row.col.f32.f16.f16.f32 "
        "{%0,%1,%2,%3}, {%4,%5,%6,%7}, {%8,%9}, {%0,%1,%2,%3};"
        : "+f"(c[0]), "+f"(c[1]), "+f"(c[2]), "+f"(c[3])
        : "r"(a[0]), "r"(a[1]), "r"(a[2]), "r"(a[3]), "r"(b0), "r"(b1));
}

__device__ __forceinline__ void split_bf(float v, __nv_bfloat16& h, __nv_bfloat16& l) {
    h = __float2bfloat16_rn(v);
    l = __float2bfloat16_rn(v - __bfloat162float(h));
}
__device__ __forceinline__ uint32_t pk(__nv_bfloat16 a, __nv_bfloat16 b) {
    __nv_bfloat162 t = __halves2bfloat162(a, b);
    uint32_t u;
    *reinterpret_cast<__nv_bfloat162*>(&u) = t;
    return u;
}
__device__ __forceinline__ uint32_t pkh(__half a, __half b) {
    __half2 t = __halves2half2(a, b);
    uint32_t u;
    *reinterpret_cast<__half2*>(&u) = t;
    return u;
}

// swizzled byte offsets: 256B rows (16 chunks of 16B), 128B rows (8 chunks)
__device__ __forceinline__ uint32_t swz_q(int row, int ch) {
    return (uint32_t)(row * 256 + ((ch ^ (row & 7)) << 4));
}
__device__ __forceinline__ uint32_t swz_v(int row, int ch) {
    return (uint32_t)(row * 128 + ((ch ^ (row & 7)) << 4));
}

// ---------------------------------------------------------------------------
// x split/transpose: x [b][c][n] fp32 -> g_xhi/g_xlo [b][n][c] bf16.
// grid (NT/64, Cc/64, Bb), 256 threads; 64x64 tiles through smem.
// ---------------------------------------------------------------------------
__global__ __launch_bounds__(256) void xsplit_kernel(const float* __restrict__ x)
{
    __shared__ float T[64][65];
    const int b  = blockIdx.z;
    const int c0 = blockIdx.y * 64;
    const int n0 = blockIdx.x * 64;
    const int tid = threadIdx.x;

    #pragma unroll
    for (int i = tid; i < 64 * 16; i += 256) {
        int c = i >> 4, n4 = i & 15;
        float4 v = *(const float4*)(x + ((size_t)b * Cc + c0 + c) * NT + n0 + n4 * 4);
        T[c][n4 * 4 + 0] = v.x; T[c][n4 * 4 + 1] = v.y;
        T[c][n4 * 4 + 2] = v.z; T[c][n4 * 4 + 3] = v.w;
    }
    __syncthreads();
    #pragma unroll
    for (int i = tid; i < 64 * 32; i += 256) {
        int n = i >> 5, c2 = i & 31;
        float f0 = T[c2 * 2][n], f1 = T[c2 * 2 + 1][n];
        __nv_bfloat16 h0, l0, h1, l1;
        split_bf(f0, h0, l0);
        split_bf(f1, h1, l1);
        size_t off = ((size_t)b * NT + n0 + n) * Cc + c0 + c2 * 2;
        *(uint32_t*)(g_xhi + off) = pk(h0, h1);
        *(uint32_t*)(g_xlo + off) = pk(l0, l1);
    }
}

// ---------------------------------------------------------------------------
// Tensor-core QKV projection (split-bf16, 3-pass), A pre-split via cp.async.
// grid (NT/128, 3, Bb), 256 threads.
// smem: Ahi[2]@0 (16K each), Alo[2]@32K, Bhi@64K, Blo@80K  -> 96KB
// ---------------------------------------------------------------------------
#define PA_HI 0
#define PA_LO 32768
#define PB_HI 65536
#define PB_LO 81920
#define P_SMEM 98304
#define ABUF 16384

extern __shared__ char proj_sm[];

__global__ __launch_bounds__(256, 1) void proj_mma_kernel(
    const float* __restrict__ Wq,
    const float* __restrict__ Wk,
    const float* __restrict__ Wv)
{
    const int b  = blockIdx.z;
    const int wi = blockIdx.y;            // 0=Q 1=K 2=V
    const int n0 = blockIdx.x * 128;
    const float* W = (wi == 0) ? Wq : (wi == 1) ? Wk : Wv;

    const int tid  = threadIdx.x;
    const int w    = tid >> 5;
    const int lane = tid & 31;
    const int q0   = w * 16;

    char* psm = proj_sm;
    const uint32_t sb = smem_u32(psm);

    const int a_row = q0 + (lane & 15);
    const int a_c16 = lane >> 4;
    const int b_row = (lane & 7) + ((lane >> 4) << 3);
    const int b_ch  = (lane >> 3) & 1;

    // prefetch A chunk 0
    {
        const char* srcH = (const char*)(g_xhi + ((size_t)b * NT + n0) * Cc);
        const char* srcL = (const char*)(g_xlo + ((size_t)b * NT + n0) * Cc);
        #pragma unroll
        for (int i = tid; i < 128 * 8; i += 256) {
            int row = i >> 3, ch = i & 7;
            CP_ASYNC16(sb + PA_HI + swz_v(row, ch), srcH + (size_t)row * Cc * 2 + ch * 16);
            CP_ASYNC16(sb + PA_LO + swz_v(row, ch), srcL + (size_t)row * Cc * 2 + ch * 16);
        }
        CP_COMMIT();
    }

    float C[16][4];
    #pragma unroll
    for (int i = 0; i < 16; i++)
        #pragma unroll
        for (int j = 0; j < 4; j++) C[i][j] = 0.f;

    #pragma unroll 1
    for (int kc = 0; kc < 4; kc++) {
        const int buf = kc & 1;
        const int c0 = kc * 64;
        // prefetch next A chunk
        if (kc + 1 < 4) {
            const char* srcH = (const char*)(g_xhi + ((size_t)b * NT + n0) * Cc) + (c0 + 64) * 2;
            const char* srcL = (const char*)(g_xlo + ((size_t)b * NT + n0) * Cc) + (c0 + 64) * 2;
            uint32_t dH = sb + PA_HI + (buf ^ 1) * ABUF;
            uint32_t dL = sb + PA_LO + (buf ^ 1) * ABUF;
            #pragma unroll
            for (int i = tid; i < 128 * 8; i += 256) {
                int row = i >> 3, ch = i & 7;
                CP_ASYNC16(dH + swz_v(row, ch), srcH + (size_t)row * Cc * 2 + ch * 16);
                CP_ASYNC16(dL + swz_v(row, ch), srcL + (size_t)row * Cc * 2 + ch * 16);
            }
        }
        CP_COMMIT();

        // build B (W split) for this chunk
        {
            const int nn = tid & 127, cg = tid >> 7;
            #pragma unroll
            for (int oc = cg; oc < 8; oc += 2) {
                const float* wrow = W + (size_t)nn * Cc + c0 + oc * 8;
                float4 wa = *(const float4*)wrow;
                float4 wb = *(const float4*)(wrow + 4);
                float g[8] = {wa.x, wa.y, wa.z, wa.w, wb.x, wb.y, wb.z, wb.w};
                uint32_t hw[4], lw[4];
                #pragma unroll
                for (int j = 0; j < 4; j++) {
                    __nv_bfloat16 h0, l0, h1, l1;
                    split_bf(g[2 * j], h0, l0);
                    split_bf(g[2 * j + 1], h1, l1);
                    hw[j] = pk(h0, h1); lw[j] = pk(l0, l1);
                }
                *(uint4*)(psm + PB_HI + swz_v(nn, oc)) = make_uint4(hw[0], hw[1], hw[2], hw[3]);
                *(uint4*)(psm + PB_LO + swz_v(nn, oc)) = make_uint4(lw[0], lw[1], lw[2], lw[3]);
            }
        }
        CP_WAIT1();
        __syncthreads();

        const uint32_t ah_base = sb + PA_HI + buf * ABUF;
        const uint32_t al_base = sb + PA_LO + buf * ABUF;

        #pragma unroll
        for (int kk = 0; kk < 4; kk++) {
            uint32_t ah[4], al[4];
            ldsm_x4(ah_base + swz_v(a_row, 2 * kk + a_c16), ah[0], ah[1], ah[2], ah[3]);
            ldsm_x4(al_base + swz_v(a_row, 2 * kk + a_c16), al[0], al[1], al[2], al[3]);
            #pragma unroll
            for (int nt = 0; nt < 8; nt++) {
                uint32_t bh0, bh1, bh2, bh3, bl0, bl1, bl2, bl3;
                ldsm_x4(sb + PB_HI + swz_v(nt * 16 + b_row, 2 * kk + b_ch), bh0, bh1, bh2, bh3);
                ldsm_x4(sb + PB_LO + swz_v(nt * 16 + b_row, 2 * kk + b_ch), bl0, bl1, bl2, bl3);
                mma_bf16(C[2 * nt],     ah, bh0, bh1);
                mma_bf16(C[2 * nt + 1], ah, bh2, bh3);
                mma_bf16(C[2 * nt],     ah, bl0, bl1);
                mma_bf16(C[2 * nt + 1], ah, bl2, bl3);
                mma_bf16(C[2 * nt],     al, bh0, bh1);
                mma_bf16(C[2 * nt + 1], al, bh2, bh3);
            }
        }
        __syncthreads();   // B reuse protection
    }

    // ---- epilogue ----
    const int r  = lane >> 2;
    const int cq = (lane & 3) * 2;

    if (wi < 2) {
        __nv_bfloat16* Bh = (wi == 0) ? g_Qhi : g_Khi;
        __nv_bfloat16* Bl = (wi == 0) ? g_Qlo : g_Klo;
        const float sc = (wi == 0) ? LOG2E : 1.0f;
        #pragma unroll
        for (int nt = 0; nt < 16; nt++) {
            int d = nt * 8 + cq;
            __nv_bfloat16 h0, l0, h1, l1;
            split_bf(C[nt][0] * sc, h0, l0);
            split_bf(C[nt][1] * sc, h1, l1);
            size_t o0 = ((size_t)b * NT + n0 + q0 + r) * VC + d;
            *(uint32_t*)(Bh + o0) = pk(h0, h1);
            *(uint32_t*)(Bl + o0) = pk(l0, l1);
            split_bf(C[nt][2] * sc, h0, l0);
            split_bf(C[nt][3] * sc, h1, l1);
            size_t o1 = o0 + (size_t)8 * VC;
            *(uint32_t*)(Bh + o1) = pk(h0, h1);
            *(uint32_t*)(Bl + o1) = pk(l0, l1);
        }
    } else {
        // V: transpose through smem (reuse A region), store fp16 [b][d][n]
        float* Vt = (float*)psm;   // 64 x 132 floats = 33792B < 64KB
        #pragma unroll
        for (int h = 0; h < 2; h++) {
            __syncthreads();
            #pragma unroll
            for (int nt = h * 8; nt < h * 8 + 8; nt++) {
                int dl = nt * 8 + cq - h * 64;
                Vt[dl * 132 + q0 + r]           = C[nt][0];
                Vt[(dl + 1) * 132 + q0 + r]     = C[nt][1];
                Vt[dl * 132 + q0 + r + 8]       = C[nt][2];
                Vt[(dl + 1) * 132 + q0 + r + 8] = C[nt][3];
            }
            __syncthreads();
            #pragma unroll
            for (int i = tid; i < 64 * 64; i += 256) {
                int dd = i >> 6, n2 = i & 63;
                __half2 hv = __floats2half2_rn(Vt[dd * 132 + n2 * 2],
                                               Vt[dd * 132 + n2 * 2 + 1]);
                *(__half2*)(g_V + ((size_t)b * VC + h * 64 + dd) * NT + n0 + n2 * 2) = hv;
            }
        }
    }
}

// ---------------------------------------------------------------------------
// Flash attention: bf16 3-pass S + fp16 single-pass PV, online-max (base-2).
// smem (160KB): Qhi 0, Qlo 32K, Khi[2] 64K, Klo[2] 96K, V[2] 128K..160K
// ---------------------------------------------------------------------------
#define QHI_OFF 0
#define QLO_OFF 32768
#define KHI_OFF 65536
#define KLO_OFF 98304
#define V_OFF   131072
#define KBUF 16384
#define S_TOTAL 163840

extern __shared__ char fa_sm[];

__device__ __forceinline__ void load_kv(uint32_t sbase, int b, int t, int buf, int tid)
{
    const int k0 = t * BN;
    #pragma unroll
    for (int comp = 0; comp < 2; comp++) {
        const __nv_bfloat16* src = comp ? g_Klo : g_Khi;
        uint32_t dst = sbase + (comp ? KLO_OFF : KHI_OFF) + buf * KBUF;
        #pragma unroll
        for (int i = tid; i < 64 * 16; i += 256) {
            int row = i >> 4, ch = i & 15;
            const char* g = (const char*)(src + ((size_t)b * NT + k0 + row) * VC) + ch * 16;
            CP_ASYNC16(dst + swz_q(row, ch), g);
        }
    }
    {
        uint32_t dst = sbase + V_OFF + buf * KBUF;
        #pragma unroll
        for (int i = tid; i < 128 * 8; i += 256) {
            int row = i >> 3, ch = i & 7;
            const char* g = (const char*)(g_V + ((size_t)b * VC + row) * NT + k0) + ch * 16;
            CP_ASYNC16(dst + swz_v(row, ch), g);
        }
    }
}

__global__ __launch_bounds__(256, 1) void fa_kernel(float* __restrict__ out)
{
    const int tid  = threadIdx.x;
    const int w    = tid >> 5;
    const int lane = tid & 31;
    const int b    = blockIdx.y;
    const int n0   = blockIdx.x * BM;
    const int q0   = w * 16;

    char* sm = fa_sm;
    const uint32_t sbase = smem_u32(sm);

    // stage Q (hi/lo)
    #pragma unroll
    for (int comp = 0; comp < 2; comp++) {
        const __nv_bfloat16* src = comp ? g_Qlo : g_Qhi;
        uint32_t dst = sbase + (comp ? QLO_OFF : QHI_OFF);
        #pragma unroll
        for (int i = tid; i < 128 * 16; i += 256) {
            int row = i >> 4, ch = i & 15;
            const char* g = (const char*)(src + ((size_t)b * NT + n0 + row) * VC) + ch * 16;
            CP_ASYNC16(dst + swz_q(row, ch), g);
        }
    }
    load_kv(sbase, b, 0, 0, tid);
    CP_COMMIT();

    float O[16][4];
    #pragma unroll
    for (int i = 0; i < 16; i++)
        #pragma unroll
        for (int j = 0; j < 4; j++) O[i][j] = 0.f;
    float rs0 = 0.f, rs1 = 0.f;
    float M0 = -1e30f, M1 = -1e30f;

    const int a_row = q0 + (lane & 15);
    const int a_ch  = (lane >> 4);
    const int b_row = (lane & 7) + ((lane >> 4) << 3);
    const int b_ch  = ((lane >> 3) & 1);

    #pragma unroll 1
    for (int t = 0; t < NTILES; t++) {
        const int buf = t & 1;
        if (t + 1 < NTILES) load_kv(sbase, b, t + 1, buf ^ 1, tid);
        CP_COMMIT();
        CP_WAIT1();
        __syncthreads();

        const uint32_t kh_base = sbase + KHI_OFF + buf * KBUF;
        const uint32_t kl_base = sbase + KLO_OFF + buf * KBUF;
        const uint32_t v_base  = sbase + V_OFF   + buf * KBUF;

        // ---- S = Q K^T (bf16 3-pass), base-2 logits (Q pre-scaled) ----
        float C[8][4];
        #pragma unroll
        for (int i = 0; i < 8; i++)
            #pragma unroll
            for (int j = 0; j < 4; j++) C[i][j] = 0.f;

        #pragma unroll
        for (int kc = 0; kc < 8; kc++) {
            uint32_t aqh[4], aql[4];
            ldsm_x4(sbase + QHI_OFF + swz_q(a_row, 2 * kc + a_ch),
                    aqh[0], aqh[1], aqh[2], aqh[3]);
            ldsm_x4(sbase + QLO_OFF + swz_q(a_row, 2 * kc + a_ch),
                    aql[0], aql[1], aql[2], aql[3]);
            #pragma unroll
            for (int ntp = 0; ntp < 4; ntp++) {
                uint32_t bh0, bh1, bh2, bh3, bl0, bl1, bl2, bl3;
                ldsm_x4(kh_base + swz_q(ntp * 16 + b_row, 2 * kc + b_ch),
                        bh0, bh1, bh2, bh3);
                ldsm_x4(kl_base + swz_q(ntp * 16 + b_row, 2 * kc + b_ch),
                        bl0, bl1, bl2, bl3);
                mma_bf16(C[2 * ntp],     aqh, bh0, bh1);
                mma_bf16(C[2 * ntp + 1], aqh, bh2, bh3);
                mma_bf16(C[2 * ntp],     aqh, bl0, bl1);
                mma_bf16(C[2 * ntp + 1], aqh, bl2, bl3);
                mma_bf16(C[2 * ntp],     aql, bh0, bh1);
                mma_bf16(C[2 * ntp + 1], aql, bh2, bh3);
            }
        }

        // ---- online softmax (base-2), P -> fp16 ----
        float tm0 = -1e30f, tm1 = -1e30f;
        #pragma unroll
        for (int nt = 0; nt < 8; nt++) {
            tm0 = fmaxf(tm0, fmaxf(C[nt][0], C[nt][1]));
            tm1 = fmaxf(tm1, fmaxf(C[nt][2], C[nt][3]));
        }
        tm0 = fmaxf(tm0, __shfl_xor_sync(0xffffffffu, tm0, 1));
        tm0 = fmaxf(tm0, __shfl_xor_sync(0xffffffffu, tm0, 2));
        tm1 = fmaxf(tm1, __shfl_xor_sync(0xffffffffu, tm1, 1));
        tm1 = fmaxf(tm1, __shfl_xor_sync(0xffffffffu, tm1, 2));
        const float M0n = fmaxf(M0, tm0);
        const float M1n = fmaxf(M1, tm1);
        const float s0 = exp2f(M0 - M0n);
        const float s1 = exp2f(M1 - M1n);
        M0 = M0n; M1 = M1n;
        rs0 *= s0; rs1 *= s1;

        uint32_t Phi[8][2];
        #pragma unroll
        for (int nt = 0; nt < 8; nt++) {
            float p0 = exp2f(C[nt][0] - M0);
            float p1 = exp2f(C[nt][1] - M0);
            float p2 = exp2f(C[nt][2] - M1);
            float p3 = exp2f(C[nt][3] - M1);
            rs0 += p0 + p1;
            rs1 += p2 + p3;
            Phi[nt][0] = pkh(__float2half_rn(p0), __float2half_rn(p1));
            Phi[nt][1] = pkh(__float2half_rn(p2), __float2half_rn(p3));
        }

        // rescale O only when the max actually moved (warp-uniform check)
        if (!__all_sync(0xffffffffu, (s0 == 1.0f) & (s1 == 1.0f))) {
            #pragma unroll
            for (int nt = 0; nt < 16; nt++) {
                O[nt][0] *= s0; O[nt][1] *= s0;
                O[nt][2] *= s1; O[nt][3] *= s1;
            }
        }

        // ---- O += P V (fp16 single pass) ----
        #pragma unroll
        for (int kc = 0; kc < 4; kc++) {
            uint32_t aph[4] = {Phi[2 * kc][0], Phi[2 * kc][1],
                               Phi[2 * kc + 1][0], Phi[2 * kc + 1][1]};
            #pragma unroll
            for (int ntp = 0; ntp < 8; ntp++) {
                uint32_t v0, v1, v2, v3;
                ldsm_x4(v_base + swz_v(ntp * 16 + b_row, 2 * kc + b_ch),
                        v0, v1, v2, v3);
                mma_f16(O[2 * ntp],     aph, v0, v1);
                mma_f16(O[2 * ntp + 1], aph, v2, v3);
            }
        }
        __syncthreads();
    }

    // ---- finalize ----
    rs0 += __shfl_xor_sync(0xffffffffu, rs0, 1);
    rs0 += __shfl_xor_sync(0xffffffffu, rs0, 2);
    rs1 += __shfl_xor_sync(0xffffffffu, rs1, 1);
    rs1 += __shfl_xor_sync(0xffffffffu, rs1, 2);
    const float inv0 = 1.0f / rs0;
    const float inv1 = 1.0f / rs1;

    __syncthreads();
    float* Ot = (float*)(sm + KHI_OFF);   // 128x132 floats fits in K/V region
    const int r  = lane >> 2;
    const int cc = (lane & 3) * 2;
    #pragma unroll
    for (int nt = 0; nt < 16; nt++) {
        int d = nt * 8 + cc;
        Ot[d * 132 + q0 + r]           = O[nt][0] * inv0;
        Ot[(d + 1) * 132 + q0 + r]     = O[nt][1] * inv0;
        Ot[d * 132 + q0 + r + 8]       = O[nt][2] * inv1;
        Ot[(d + 1) * 132 + q0 + r + 8] = O[nt][3] * inv1;
    }
    __syncthreads();

    float* outb = out + (size_t)b * VC * NT;
    #pragma unroll
    for (int i = tid; i < VC * BM; i += 256) {
        int d = i >> 7, q = i & 127;
        outb[(size_t)d * NT + n0 + q] = Ot[d * 132 + q];
    }
}

// ---------------------------------------------------------------------------
extern "C" void kernel_launch(void* const* d_in, const int* in_sizes, int n_in,
                              void* d_out, int out_size)
{
    const float* x  = (const float*)d_in[0];
    const float* Wq = (const float*)d_in[1];
    const float* Wk = (const float*)d_in[2];
    const float* Wv = (const float*)d_in[3];
    float* out = (float*)d_out;

    dim3 g0(NT / 64, Cc / 64, Bb);
    xsplit_kernel<<<g0, 256>>>(x);

    cudaFuncSetAttribute(proj_mma_kernel, cudaFuncAttributeMaxDynamicSharedMemorySize, P_SMEM);
    dim3 g1(NT / 128, 3, Bb);
    proj_mma_kernel<<<g1, 256, P_SMEM>>>(Wq, Wk, Wv);

    cudaFuncSetAttribute(fa_kernel, cudaFuncAttributeMaxDynamicSharedMemorySize, S_TOTAL);
    dim3 g2(NT / BM, Bb);
    fa_kernel<<<g2, 256, S_TOTAL>>>(out);
}

// round 8
// speedup vs baseline: 4.4580x; 1.0699x over previous
#include <cuda_runtime.h>
#include <cuda_bf16.h>
#include <cuda_fp16.h>
#include <cstdint>

// ---------------------------------------------------------------------------
// Problem constants
// ---------------------------------------------------------------------------
#define Bb 4
#define Cc 256
#define VC 128
#define NT 4096          // H*W
#define BM 128           // queries per CTA
#define BN 64            // keys per tile
#define NTILES (NT / BN) // 64
#define LOG2E 1.4426950408889634f

// Scratch
__device__ __nv_bfloat16 g_xhi[Bb * NT * Cc];   // x split, [b][n][c]
__device__ __nv_bfloat16 g_xlo[Bb * NT * Cc];
__device__ __nv_bfloat16 g_Whi[3 * VC * Cc];    // W split, [wi][d][c]
__device__ __nv_bfloat16 g_Wlo[3 * VC * Cc];
__device__ __nv_bfloat16 g_Qhi[Bb * NT * VC];   // Q*log2e split, [b][n][d]
__device__ __nv_bfloat16 g_Qlo[Bb * NT * VC];
__device__ __nv_bfloat16 g_Khi[Bb * NT * VC];
__device__ __nv_bfloat16 g_Klo[Bb * NT * VC];
__device__ __half        g_V  [Bb * VC * NT];   // V fp16, [b][d][n]

// ---------------------------------------------------------------------------
// helpers
// ---------------------------------------------------------------------------
__device__ __forceinline__ uint32_t smem_u32(const void* p) {
    uint32_t a;
    asm("{ .reg .u64 t; cvta.to.shared.u64 t, %1; cvt.u32.u64 %0, t; }"
        : "=r"(a) : "l"(p));
    return a;
}

#define CP_ASYNC16(dst, src) \
    asm volatile("cp.async.cg.shared.global [%0], [%1], 16;" \
                 :: "r"(dst), "l"(src) : "memory")
#define CP_COMMIT() asm volatile("cp.async.commit_group;" ::: "memory")
#define CP_WAIT1()  asm volatile("cp.async.wait_group 1;" ::: "memory")
#define CP_WAIT0()  asm volatile("cp.async.wait_group 0;" ::: "memory")

__device__ __forceinline__ void ldsm_x4(uint32_t addr, uint32_t& r0, uint32_t& r1,
                                        uint32_t& r2, uint32_t& r3) {
    asm volatile("ldmatrix.sync.aligned.m8n8.x4.shared.b16 {%0,%1,%2,%3}, [%4];"
                 : "=r"(r0), "=r"(r1), "=r"(r2), "=r"(r3) : "r"(addr));
}

__device__ __forceinline__ void mma_bf16(float* c, const uint32_t a[4],
                                         uint32_t b0, uint32_t b1) {
    asm volatile(
        "mma.sync.aligned.m16n8k16.row.col.f32.bf16.bf16.f32 "
        "{%0,%1,%2,%3}, {%4,%5,%6,%7}, {%8,%9}, {%0,%1,%2,%3};"
        : "+f"(c[0]), "+f"(c[1]), "+f"(c[2]), "+f"(c[3])
        : "r"(a[0]), "r"(a[1]), "r"(a[2]), "r"(a[3]), "r"(b0), "r"(b1));
}
__device__ __forceinline__ void mma_f16(float* c, const uint32_t a[4],
                                        uint32_t b0, uint32_t b1) {
    asm volatile(
        "mma.sync.aligned.m16n8k16.row.col.f32.f16.f16.f32 "
        "{%0,%1,%2,%3}, {%4,%5,%6,%7}, {%8,%9}, {%0,%1,%2,%3};"
        : "+f"(c[0]), "+f"(c[1]), "+f"(c[2]), "+f"(c[3])
        : "r"(a[0]), "r"(a[1]), "r"(a[2]), "r"(a[3]), "r"(b0), "r"(b1));
}

__device__ __forceinline__ void split_bf(float v, __nv_bfloat16& h, __nv_bfloat16& l) {
    h = __float2bfloat16_rn(v);
    l = __float2bfloat16_rn(v - __bfloat162float(h));
}
__device__ __forceinline__ uint32_t pk(__nv_bfloat16 a, __nv_bfloat16 b) {
    __nv_bfloat162 t = __halves2bfloat162(a, b);
    uint32_t u;
    *reinterpret_cast<__nv_bfloat162*>(&u) = t;
    return u;
}
__device__ __forceinline__ uint32_t pkh(__half a, __half b) {
    __half2 t = __halves2half2(a, b);
    uint32_t u;
    *reinterpret_cast<__half2*>(&u) = t;
    return u;
}

// swizzled byte offsets: 256B rows (16 chunks of 16B), 128B rows (8 chunks)
__device__ __forceinline__ uint32_t swz_q(int row, int ch) {
    return (uint32_t)(row * 256 + ((ch ^ (row & 7)) << 4));
}
__device__ __forceinline__ uint32_t swz_v(int row, int ch) {
    return (uint32_t)(row * 128 + ((ch ^ (row & 7)) << 4));
}

// ---------------------------------------------------------------------------
// W split: Wq/Wk/Wv [d][c] fp32 -> g_Whi/g_Wlo bf16 [wi][d][c]
// ---------------------------------------------------------------------------
__global__ __launch_bounds__(256) void wsplit_kernel(
    const float* __restrict__ Wq,
    const float* __restrict__ Wk,
    const float* __restrict__ Wv)
{
    const int idx = blockIdx.x * 256 + threadIdx.x;   // one float4 each
    const int f0  = idx * 4;
    const int wi  = f0 / (VC * Cc);
    const int off = f0 - wi * (VC * Cc);
    const float* W = (wi == 0) ? Wq : (wi == 1) ? Wk : Wv;
    float4 v = *(const float4*)(W + off);
    __nv_bfloat16 h0, l0, h1, l1, h2, l2, h3, l3;
    split_bf(v.x, h0, l0); split_bf(v.y, h1, l1);
    split_bf(v.z, h2, l2); split_bf(v.w, h3, l3);
    size_t o = (size_t)wi * VC * Cc + off;
    *(uint2*)(g_Whi + o) = make_uint2(pk(h0, h1), pk(h2, h3));
    *(uint2*)(g_Wlo + o) = make_uint2(pk(l0, l1), pk(l2, l3));
}

// ---------------------------------------------------------------------------
// x split/transpose: x [b][c][n] fp32 -> g_xhi/g_xlo [b][n][c] bf16.
// ---------------------------------------------------------------------------
__global__ __launch_bounds__(256) void xsplit_kernel(const float* __restrict__ x)
{
    __shared__ float T[64][65];
    const int b  = blockIdx.z;
    const int c0 = blockIdx.y * 64;
    const int n0 = blockIdx.x * 64;
    const int tid = threadIdx.x;

    #pragma unroll
    for (int i = tid; i < 64 * 16; i += 256) {
        int c = i >> 4, n4 = i & 15;
        float4 v = *(const float4*)(x + ((size_t)b * Cc + c0 + c) * NT + n0 + n4 * 4);
        T[c][n4 * 4 + 0] = v.x; T[c][n4 * 4 + 1] = v.y;
        T[c][n4 * 4 + 2] = v.z; T[c][n4 * 4 + 3] = v.w;
    }
    __syncthreads();
    #pragma unroll
    for (int i = tid; i < 64 * 32; i += 256) {
        int n = i >> 5, c2 = i & 31;
        float f0 = T[c2 * 2][n], f1 = T[c2 * 2 + 1][n];
        __nv_bfloat16 h0, l0, h1, l1;
        split_bf(f0, h0, l0);
        split_bf(f1, h1, l1);
        size_t off = ((size_t)b * NT + n0 + n) * Cc + c0 + c2 * 2;
        *(uint32_t*)(g_xhi + off) = pk(h0, h1);
        *(uint32_t*)(g_xlo + off) = pk(l0, l1);
    }
}

// ---------------------------------------------------------------------------
// Fused QKV projection (split-bf16, 3-pass). One CTA per 128-row n-block:
// A (x) staged ONCE for all 4 K-chunks (hi+lo, 128KB), then 12 iterations
// (wi 0..2 x kc 0..3) with double-buffered W tiles (32KB each).
// grid (NT/128, Bb), 256 threads, smem 192KB.
// ---------------------------------------------------------------------------
#define FA_OFF(kc, comp) (((kc) * 2 + (comp)) * 16384)
#define FB_OFF 131072
#define FB_BUF 32768
#define PF_SMEM 196608

extern __shared__ char proj_sm[];

__device__ __forceinline__ void proj_load_B(uint32_t sb, int wi, int kc, int buf, int tid)
{
    #pragma unroll
    for (int i = tid; i < 2048; i += 256) {
        int comp = i >> 10, row = (i >> 3) & 127, ch = i & 7;
        const __nv_bfloat16* src = comp ? g_Wlo : g_Whi;
        const char* g = (const char*)(src + (size_t)wi * VC * Cc + (size_t)row * Cc + kc * 64)
                        + ch * 16;
        CP_ASYNC16(sb + FB_OFF + buf * FB_BUF + comp * 16384 + swz_v(row, ch), g);
    }
}

__global__ __launch_bounds__(256, 1) void proj_fused_kernel()
{
    const int b  = blockIdx.y;
    const int n0 = blockIdx.x * 128;

    const int tid  = threadIdx.x;
    const int w    = tid >> 5;
    const int lane = tid & 31;
    const int q0   = w * 16;

    char* psm = proj_sm;
    const uint32_t sb = smem_u32(psm);

    const int a_row = q0 + (lane & 15);
    const int a_c16 = lane >> 4;
    const int b_row = (lane & 7) + ((lane >> 4) << 3);
    const int b_ch  = (lane >> 3) & 1;

    // stage ALL A chunks (hi+lo) + B(0); one commit group
    #pragma unroll
    for (int i = tid; i < 8192; i += 256) {
        int comp = i >> 12;
        int rem  = i & 4095;
        int kc   = rem >> 10;
        int row  = (rem >> 3) & 127;
        int ch   = rem & 7;
        const __nv_bfloat16* src = comp ? g_xlo : g_xhi;
        const char* g = (const char*)(src + ((size_t)b * NT + n0 + row) * Cc + kc * 64)
                        + ch * 16;
        CP_ASYNC16(sb + FA_OFF(kc, comp) + swz_v(row, ch), g);
    }
    proj_load_B(sb, 0, 0, 0, tid);
    CP_COMMIT();

    float C[16][4];
    const int r  = lane >> 2;
    const int cq = (lane & 3) * 2;

    #pragma unroll 1
    for (int it = 0; it < 12; it++) {
        const int wi  = it >> 2;
        const int kc  = it & 3;
        const int buf = it & 1;

        if (kc == 0) {
            #pragma unroll
            for (int i = 0; i < 16; i++)
                #pragma unroll
                for (int j = 0; j < 4; j++) C[i][j] = 0.f;
        }

        __syncthreads();   // all warps done reading buf^1 (previous tile)
        if (it + 1 < 12) {
            proj_load_B(sb, (it + 1) >> 2, (it + 1) & 3, buf ^ 1, tid);
            CP_COMMIT();
            CP_WAIT1();
        } else {
            CP_WAIT0();
        }
        __syncthreads();

        const uint32_t bh_base = sb + FB_OFF + buf * FB_BUF;
        const uint32_t bl_base = bh_base + 16384;
        const uint32_t ah_base = sb + FA_OFF(kc, 0);
        const uint32_t al_base = sb + FA_OFF(kc, 1);

        #pragma unroll
        for (int kk = 0; kk < 4; kk++) {
            uint32_t ah[4], al[4];
            ldsm_x4(ah_base + swz_v(a_row, 2 * kk + a_c16), ah[0], ah[1], ah[2], ah[3]);
            ldsm_x4(al_base + swz_v(a_row, 2 * kk + a_c16), al[0], al[1], al[2], al[3]);
            #pragma unroll
            for (int nt = 0; nt < 8; nt++) {
                uint32_t bh0, bh1, bh2, bh3, bl0, bl1, bl2, bl3;
                ldsm_x4(bh_base + swz_v(nt * 16 + b_row, 2 * kk + b_ch), bh0, bh1, bh2, bh3);
                ldsm_x4(bl_base + swz_v(nt * 16 + b_row, 2 * kk + b_ch), bl0, bl1, bl2, bl3);
                mma_bf16(C[2 * nt],     ah, bh0, bh1);
                mma_bf16(C[2 * nt + 1], ah, bh2, bh3);
                mma_bf16(C[2 * nt],     ah, bl0, bl1);
                mma_bf16(C[2 * nt + 1], ah, bl2, bl3);
                mma_bf16(C[2 * nt],     al, bh0, bh1);
                mma_bf16(C[2 * nt + 1], al, bh2, bh3);
            }
        }

        if (kc == 3) {
            if (wi < 2) {
                __nv_bfloat16* Bh = (wi == 0) ? g_Qhi : g_Khi;
                __nv_bfloat16* Bl = (wi == 0) ? g_Qlo : g_Klo;
                const float sc = (wi == 0) ? LOG2E : 1.0f;
                #pragma unroll
                for (int nt = 0; nt < 16; nt++) {
                    int d = nt * 8 + cq;
                    __nv_bfloat16 h0, l0, h1, l1;
                    split_bf(C[nt][0] * sc, h0, l0);
                    split_bf(C[nt][1] * sc, h1, l1);
                    size_t o0 = ((size_t)b * NT + n0 + q0 + r) * VC + d;
                    *(uint32_t*)(Bh + o0) = pk(h0, h1);
                    *(uint32_t*)(Bl + o0) = pk(l0, l1);
                    split_bf(C[nt][2] * sc, h0, l0);
                    split_bf(C[nt][3] * sc, h1, l1);
                    size_t o1 = o0 + (size_t)8 * VC;
                    *(uint32_t*)(Bh + o1) = pk(h0, h1);
                    *(uint32_t*)(Bl + o1) = pk(l0, l1);
                }
            } else {
                // V: transpose through smem (A region is free now), fp16 [b][d][n]
                float* Vt = (float*)psm;   // 64 x 132 floats
                #pragma unroll
                for (int h = 0; h < 2; h++) {
                    __syncthreads();
                    #pragma unroll
                    for (int nt = h * 8; nt < h * 8 + 8; nt++) {
                        int dl = nt * 8 + cq - h * 64;
                        Vt[dl * 132 + q0 + r]           = C[nt][0];
                        Vt[(dl + 1) * 132 + q0 + r]     = C[nt][1];
                        Vt[dl * 132 + q0 + r + 8]       = C[nt][2];
                        Vt[(dl + 1) * 132 + q0 + r + 8] = C[nt][3];
                    }
                    __syncthreads();
                    #pragma unroll
                    for (int i = tid; i < 64 * 64; i += 256) {
                        int dd = i >> 6, n2 = i & 63;
                        __half2 hv = __floats2half2_rn(Vt[dd * 132 + n2 * 2],
                                                       Vt[dd * 132 + n2 * 2 + 1]);
                        *(__half2*)(g_V + ((size_t)b * VC + h * 64 + dd) * NT + n0 + n2 * 2) = hv;
                    }
                }
            }
        }
    }
}

// ---------------------------------------------------------------------------
// Flash attention: bf16 3-pass S + fp16 single-pass PV, online-max (base-2).
// smem (160KB): Qhi 0, Qlo 32K, Khi[2] 64K, Klo[2] 96K, V[2] 128K..160K
// ---------------------------------------------------------------------------
#define QHI_OFF 0
#define QLO_OFF 32768
#define KHI_OFF 65536
#define KLO_OFF 98304
#define V_OFF   131072
#define KBUF 16384
#define S_TOTAL 163840

extern __shared__ char fa_sm[];

__device__ __forceinline__ void load_kv(uint32_t sbase, int b, int t, int buf, int tid)
{
    const int k0 = t * BN;
    #pragma unroll
    for (int comp = 0; comp < 2; comp++) {
        const __nv_bfloat16* src = comp ? g_Klo : g_Khi;
        uint32_t dst = sbase + (comp ? KLO_OFF : KHI_OFF) + buf * KBUF;
        #pragma unroll
        for (int i = tid; i < 64 * 16; i += 256) {
            int row = i >> 4, ch = i & 15;
            const char* g = (const char*)(src + ((size_t)b * NT + k0 + row) * VC) + ch * 16;
            CP_ASYNC16(dst + swz_q(row, ch), g);
        }
    }
    {
        uint32_t dst = sbase + V_OFF + buf * KBUF;
        #pragma unroll
        for (int i = tid; i < 128 * 8; i += 256) {
            int row = i >> 3, ch = i & 7;
            const char* g = (const char*)(g_V + ((size_t)b * VC + row) * NT + k0) + ch * 16;
            CP_ASYNC16(dst + swz_v(row, ch), g);
        }
    }
}

__global__ __launch_bounds__(256, 1) void fa_kernel(float* __restrict__ out)
{
    const int tid  = threadIdx.x;
    const int w    = tid >> 5;
    const int lane = tid & 31;
    const int b    = blockIdx.y;
    const int n0   = blockIdx.x * BM;
    const int q0   = w * 16;

    char* sm = fa_sm;
    const uint32_t sbase = smem_u32(sm);

    // stage Q (hi/lo)
    #pragma unroll
    for (int comp = 0; comp < 2; comp++) {
        const __nv_bfloat16* src = comp ? g_Qlo : g_Qhi;
        uint32_t dst = sbase + (comp ? QLO_OFF : QHI_OFF);
        #pragma unroll
        for (int i = tid; i < 128 * 16; i += 256) {
            int row = i >> 4, ch = i & 15;
            const char* g = (const char*)(src + ((size_t)b * NT + n0 + row) * VC) + ch * 16;
            CP_ASYNC16(dst + swz_q(row, ch), g);
        }
    }
    load_kv(sbase, b, 0, 0, tid);
    CP_COMMIT();

    float O[16][4];
    #pragma unroll
    for (int i = 0; i < 16; i++)
        #pragma unroll
        for (int j = 0; j < 4; j++) O[i][j] = 0.f;
    float rs0 = 0.f, rs1 = 0.f;
    float M0 = -1e30f, M1 = -1e30f;

    const int a_row = q0 + (lane & 15);
    const int a_ch  = (lane >> 4);
    const int b_row = (lane & 7) + ((lane >> 4) << 3);
    const int b_ch  = ((lane >> 3) & 1);

    #pragma unroll 1
    for (int t = 0; t < NTILES; t++) {
        const int buf = t & 1;
        if (t + 1 < NTILES) load_kv(sbase, b, t + 1, buf ^ 1, tid);
        CP_COMMIT();
        CP_WAIT1();
        __syncthreads();

        const uint32_t kh_base = sbase + KHI_OFF + buf * KBUF;
        const uint32_t kl_base = sbase + KLO_OFF + buf * KBUF;
        const uint32_t v_base  = sbase + V_OFF   + buf * KBUF;

        // ---- S = Q K^T (bf16 3-pass), base-2 logits (Q pre-scaled) ----
        float C[8][4];
        #pragma unroll
        for (int i = 0; i < 8; i++)
            #pragma unroll
            for (int j = 0; j < 4; j++) C[i][j] = 0.f;

        #pragma unroll
        for (int kc = 0; kc < 8; kc++) {
            uint32_t aqh[4], aql[4];
            ldsm_x4(sbase + QHI_OFF + swz_q(a_row, 2 * kc + a_ch),
                    aqh[0], aqh[1], aqh[2], aqh[3]);
            ldsm_x4(sbase + QLO_OFF + swz_q(a_row, 2 * kc + a_ch),
                    aql[0], aql[1], aql[2], aql[3]);
            #pragma unroll
            for (int ntp = 0; ntp < 4; ntp++) {
                uint32_t bh0, bh1, bh2, bh3, bl0, bl1, bl2, bl3;
                ldsm_x4(kh_base + swz_q(ntp * 16 + b_row, 2 * kc + b_ch),
                        bh0, bh1, bh2, bh3);
                ldsm_x4(kl_base + swz_q(ntp * 16 + b_row, 2 * kc + b_ch),
                        bl0, bl1, bl2, bl3);
                mma_bf16(C[2 * ntp],     aqh, bh0, bh1);
                mma_bf16(C[2 * ntp + 1], aqh, bh2, bh3);
                mma_bf16(C[2 * ntp],     aqh, bl0, bl1);
                mma_bf16(C[2 * ntp + 1], aqh, bl2, bl3);
                mma_bf16(C[2 * ntp],     aql, bh0, bh1);
                mma_bf16(C[2 * ntp + 1], aql, bh2, bh3);
            }
        }

        // ---- online softmax (base-2), P -> fp16 ----
        float tm0 = -1e30f, tm1 = -1e30f;
        #pragma unroll
        for (int nt = 0; nt < 8; nt++) {
            tm0 = fmaxf(tm0, fmaxf(C[nt][0], C[nt][1]));
            tm1 = fmaxf(tm1, fmaxf(C[nt][2], C[nt][3]));
        }
        tm0 = fmaxf(tm0, __shfl_xor_sync(0xffffffffu, tm0, 1));
        tm0 = fmaxf(tm0, __shfl_xor_sync(0xffffffffu, tm0, 2));
        tm1 = fmaxf(tm1, __shfl_xor_sync(0xffffffffu, tm1, 1));
        tm1 = fmaxf(tm1, __shfl_xor_sync(0xffffffffu, tm1, 2));
        const float M0n = fmaxf(M0, tm0);
        const float M1n = fmaxf(M1, tm1);
        const float s0 = exp2f(M0 - M0n);
        const float s1 = exp2f(M1 - M1n);
        M0 = M0n; M1 = M1n;
        rs0 *= s0; rs1 *= s1;

        uint32_t Phi[8][2];
        #pragma unroll
        for (int nt = 0; nt < 8; nt++) {
            float p0 = exp2f(C[nt][0] - M0);
            float p1 = exp2f(C[nt][1] - M0);
            float p2 = exp2f(C[nt][2] - M1);
            float p3 = exp2f(C[nt][3] - M1);
            rs0 += p0 + p1;
            rs1 += p2 + p3;
            Phi[nt][0] = pkh(__float2half_rn(p0), __float2half_rn(p1));
            Phi[nt][1] = pkh(__float2half_rn(p2), __float2half_rn(p3));
        }

        // rescale O only when the max actually moved (warp-uniform check)
        if (!__all_sync(0xffffffffu, (s0 == 1.0f) & (s1 == 1.0f))) {
            #pragma unroll
            for (int nt = 0; nt < 16; nt++) {
                O[nt][0] *= s0; O[nt][1] *= s0;
                O[nt][2] *= s1; O[nt][3] *= s1;
            }
        }

        // ---- O += P V (fp16 single pass) ----
        #pragma unroll
        for (int kc = 0; kc < 4; kc++) {
            uint32_t aph[4] = {Phi[2 * kc][0], Phi[2 * kc][1],
                               Phi[2 * kc + 1][0], Phi[2 * kc + 1][1]};
            #pragma unroll
            for (int ntp = 0; ntp < 8; ntp++) {
                uint32_t v0, v1, v2, v3;
                ldsm_x4(v_base + swz_v(ntp * 16 + b_row, 2 * kc + b_ch),
                        v0, v1, v2, v3);
                mma_f16(O[2 * ntp],     aph, v0, v1);
                mma_f16(O[2 * ntp + 1], aph, v2, v3);
            }
        }
        __syncthreads();
    }

    // ---- finalize ----
    rs0 += __shfl_xor_sync(0xffffffffu, rs0, 1);
    rs0 += __shfl_xor_sync(0xffffffffu, rs0, 2);
    rs1 += __shfl_xor_sync(0xffffffffu, rs1, 1);
    rs1 += __shfl_xor_sync(0xffffffffu, rs1, 2);
    const float inv0 = 1.0f / rs0;
    const float inv1 = 1.0f / rs1;

    __syncthreads();
    float* Ot = (float*)(sm + KHI_OFF);   // 128x132 floats fits in K/V region
    const int r  = lane >> 2;
    const int cc = (lane & 3) * 2;
    #pragma unroll
    for (int nt = 0; nt < 16; nt++) {
        int d = nt * 8 + cc;
        Ot[d * 132 + q0 + r]           = O[nt][0] * inv0;
        Ot[(d + 1) * 132 + q0 + r]     = O[nt][1] * inv0;
        Ot[d * 132 + q0 + r + 8]       = O[nt][2] * inv1;
        Ot[(d + 1) * 132 + q0 + r + 8] = O[nt][3] * inv1;
    }
    __syncthreads();

    float* outb = out + (size_t)b * VC * NT;
    #pragma unroll
    for (int i = tid; i < VC * BM; i += 256) {
        int d = i >> 7, q = i & 127;
        outb[(size_t)d * NT + n0 + q] = Ot[d * 132 + q];
    }
}

// ---------------------------------------------------------------------------
extern "C" void kernel_launch(void* const* d_in, const int* in_sizes, int n_in,
                              void* d_out, int out_size)
{
    const float* x  = (const float*)d_in[0];
    const float* Wq = (const float*)d_in[1];
    const float* Wk = (const float*)d_in[2];
    const float* Wv = (const float*)d_in[3];
    float* out = (float*)d_out;

    wsplit_kernel<<<3 * VC * Cc / 4 / 256, 256>>>(Wq, Wk, Wv);

    dim3 g0(NT / 64, Cc / 64, Bb);
    xsplit_kernel<<<g0, 256>>>(x);

    cudaFuncSetAttribute(proj_fused_kernel, cudaFuncAttributeMaxDynamicSharedMemorySize, PF_SMEM);
    dim3 g1(NT / 128, Bb);
    proj_fused_kernel<<<g1, 256, PF_SMEM>>>();

    cudaFuncSetAttribute(fa_kernel, cudaFuncAttributeMaxDynamicSharedMemorySize, S_TOTAL);
    dim3 g2(NT / BM, Bb);
    fa_kernel<<<g2, 256, S_TOTAL>>>(out);
}

// round 11
// speedup vs baseline: 4.8618x; 1.0906x over previous
#include <cuda_runtime.h>
#include <cuda_bf16.h>
#include <cuda_fp16.h>
#include <cstdint>

// ---------------------------------------------------------------------------
// Problem constants
// ---------------------------------------------------------------------------
#define Bb 4
#define Cc 256
#define VC 128
#define NT 4096          // H*W
#define BM 128           // queries per CTA
#define BN 64            // keys per tile
#define NTILES (NT / BN) // 64
#define LOG2E 1.4426950408889634f

// Scratch
__device__ __nv_bfloat16 g_xhi[Bb * NT * Cc];   // x split, [b][n][c]
__device__ __nv_bfloat16 g_xlo[Bb * NT * Cc];
__device__ __nv_bfloat16 g_Whi[3 * VC * Cc];    // W split, [wi][d][c]
__device__ __nv_bfloat16 g_Wlo[3 * VC * Cc];
__device__ __nv_bfloat16 g_Qhi[Bb * NT * VC];   // Q*log2e split, [b][n][d]
__device__ __nv_bfloat16 g_Qlo[Bb * NT * VC];
__device__ __nv_bfloat16 g_Khi[Bb * NT * VC];
__device__ __nv_bfloat16 g_Klo[Bb * NT * VC];
__device__ __half        g_V  [Bb * VC * NT];   // V fp16, [b][d][n]

// ---------------------------------------------------------------------------
// helpers
// ---------------------------------------------------------------------------
__device__ __forceinline__ uint32_t smem_u32(const void* p) {
    uint32_t a;
    asm("{ .reg .u64 t; cvta.to.shared.u64 t, %1; cvt.u32.u64 %0, t; }"
        : "=r"(a) : "l"(p));
    return a;
}
__device__ __forceinline__ float ex2(float x) {
    float y;
    asm("ex2.approx.ftz.f32 %0, %1;" : "=f"(y) : "f"(x));
    return y;
}

#define CP_ASYNC16(dst, src) \
    asm volatile("cp.async.cg.shared.global [%0], [%1], 16;" \
                 :: "r"(dst), "l"(src) : "memory")
#define CP_COMMIT() asm volatile("cp.async.commit_group;" ::: "memory")
#define CP_WAIT1()  asm volatile("cp.async.wait_group 1;" ::: "memory")
#define CP_WAIT0()  asm volatile("cp.async.wait_group 0;" ::: "memory")

__device__ __forceinline__ void ldsm_x4(uint32_t addr, uint32_t& r0, uint32_t& r1,
                                        uint32_t& r2, uint32_t& r3) {
    asm volatile("ldmatrix.sync.aligned.m8n8.x4.shared.b16 {%0,%1,%2,%3}, [%4];"
                 : "=r"(r0), "=r"(r1), "=r"(r2), "=r"(r3) : "r"(addr));
}

__device__ __forceinline__ void mma_bf16(float* c, const uint32_t a[4],
                                         uint32_t b0, uint32_t b1) {
    asm volatile(
        "mma.sync.aligned.m16n8k16.row.col.f32.bf16.bf16.f32 "
        "{%0,%1,%2,%3}, {%4,%5,%6,%7}, {%8,%9}, {%0,%1,%2,%3};"
        : "+f"(c[0]), "+f"(c[1]), "+f"(c[2]), "+f"(c[3])
        : "r"(a[0]), "r"(a[1]), "r"(a[2]), "r"(a[3]), "r"(b0), "r"(b1));
}
__device__ __forceinline__ void mma_f16(float* c, const uint32_t a[4],
                                        uint32_t b0, uint32_t b1) {
    asm volatile(
        "mma.sync.aligned.m16n8k16.row.col.f32.f16.f16.f32 "
        "{%0,%1,%2,%3}, {%4,%5,%6,%7}, {%8,%9}, {%0,%1,%2,%3};"
        : "+f"(c[0]), "+f"(c[1]), "+f"(c[2]), "+f"(c[3])
        : "r"(a[0]), "r"(a[1]), "r"(a[2]), "r"(a[3]), "r"(b0), "r"(b1));
}

__device__ __forceinline__ void split_bf(float v, __nv_bfloat16& h, __nv_bfloat16& l) {
    h = __float2bfloat16_rn(v);
    l = __float2bfloat16_rn(v - __bfloat162float(h));
}
__device__ __forceinline__ uint32_t pk(__nv_bfloat16 a, __nv_bfloat16 b) {
    __nv_bfloat162 t = __halves2bfloat162(a, b);
    uint32_t u;
    *reinterpret_cast<__nv_bfloat162*>(&u) = t;
    return u;
}
__device__ __forceinline__ uint32_t pkh(__half a, __half b) {
    __half2 t = __halves2half2(a, b);
    uint32_t u;
    *reinterpret_cast<__half2*>(&u) = t;
    return u;
}

// swizzled byte offsets: 256B rows (16 chunks of 16B), 128B rows (8 chunks)
__device__ __forceinline__ uint32_t swz_q(int row, int ch) {
    return (uint32_t)(row * 256 + ((ch ^ (row & 7)) << 4));
}
__device__ __forceinline__ uint32_t swz_v(int row, int ch) {
    return (uint32_t)(row * 128 + ((ch ^ (row & 7)) << 4));
}

// ---------------------------------------------------------------------------
// W split: Wq/Wk/Wv [d][c] fp32 -> g_Whi/g_Wlo bf16 [wi][d][c]
// ---------------------------------------------------------------------------
__global__ __launch_bounds__(256) void wsplit_kernel(
    const float* __restrict__ Wq,
    const float* __restrict__ Wk,
    const float* __restrict__ Wv)
{
    const int idx = blockIdx.x * 256 + threadIdx.x;
    const int f0  = idx * 4;
    const int wi  = f0 / (VC * Cc);
    const int off = f0 - wi * (VC * Cc);
    const float* W = (wi == 0) ? Wq : (wi == 1) ? Wk : Wv;
    float4 v = *(const float4*)(W + off);
    __nv_bfloat16 h0, l0, h1, l1, h2, l2, h3, l3;
    split_bf(v.x, h0, l0); split_bf(v.y, h1, l1);
    split_bf(v.z, h2, l2); split_bf(v.w, h3, l3);
    size_t o = (size_t)wi * VC * Cc + off;
    *(uint2*)(g_Whi + o) = make_uint2(pk(h0, h1), pk(h2, h3));
    *(uint2*)(g_Wlo + o) = make_uint2(pk(l0, l1), pk(l2, l3));
}

// ---------------------------------------------------------------------------
// x split/transpose: x [b][c][n] fp32 -> g_xhi/g_xlo [b][n][c] bf16.
// ---------------------------------------------------------------------------
__global__ __launch_bounds__(256) void xsplit_kernel(const float* __restrict__ x)
{
    __shared__ float T[64][65];
    const int b  = blockIdx.z;
    const int c0 = blockIdx.y * 64;
    const int n0 = blockIdx.x * 64;
    const int tid = threadIdx.x;

    #pragma unroll
    for (int i = tid; i < 64 * 16; i += 256) {
        int c = i >> 4, n4 = i & 15;
        float4 v = *(const float4*)(x + ((size_t)b * Cc + c0 + c) * NT + n0 + n4 * 4);
        T[c][n4 * 4 + 0] = v.x; T[c][n4 * 4 + 1] = v.y;
        T[c][n4 * 4 + 2] = v.z; T[c][n4 * 4 + 3] = v.w;
    }
    __syncthreads();
    #pragma unroll
    for (int i = tid; i < 64 * 32; i += 256) {
        int n = i >> 5, c2 = i & 31;
        float f0 = T[c2 * 2][n], f1 = T[c2 * 2 + 1][n];
        __nv_bfloat16 h0, l0, h1, l1;
        split_bf(f0, h0, l0);
        split_bf(f1, h1, l1);
        size_t off = ((size_t)b * NT + n0 + n) * Cc + c0 + c2 * 2;
        *(uint32_t*)(g_xhi + off) = pk(h0, h1);
        *(uint32_t*)(g_xlo + off) = pk(l0, l1);
    }
}

// ---------------------------------------------------------------------------
// Fused QKV projection (split-bf16, 3-pass). A staged once, B double-buffered.
// grid (NT/128, Bb), 256 threads, smem 192KB.
// ---------------------------------------------------------------------------
#define FA_OFF(kc, comp) (((kc) * 2 + (comp)) * 16384)
#define FB_OFF 131072
#define FB_BUF 32768
#define PF_SMEM 196608

extern __shared__ char proj_sm[];

__device__ __forceinline__ void proj_load_B(uint32_t sb, int wi, int kc, int buf, int tid)
{
    #pragma unroll
    for (int i = tid; i < 2048; i += 256) {
        int comp = i >> 10, row = (i >> 3) & 127, ch = i & 7;
        const __nv_bfloat16* src = comp ? g_Wlo : g_Whi;
        const char* g = (const char*)(src + (size_t)wi * VC * Cc + (size_t)row * Cc + kc * 64)
                        + ch * 16;
        CP_ASYNC16(sb + FB_OFF + buf * FB_BUF + comp * 16384 + swz_v(row, ch), g);
    }
}

__global__ __launch_bounds__(256, 1) void proj_fused_kernel()
{
    const int b  = blockIdx.y;
    const int n0 = blockIdx.x * 128;

    const int tid  = threadIdx.x;
    const int w    = tid >> 5;
    const int lane = tid & 31;
    const int q0   = w * 16;

    char* psm = proj_sm;
    const uint32_t sb = smem_u32(psm);

    const int a_row = q0 + (lane & 15);
    const int a_c16 = lane >> 4;
    const int b_row = (lane & 7) + ((lane >> 4) << 3);
    const int b_ch  = (lane >> 3) & 1;

    #pragma unroll
    for (int i = tid; i < 8192; i += 256) {
        int comp = i >> 12;
        int rem  = i & 4095;
        int kc   = rem >> 10;
        int row  = (rem >> 3) & 127;
        int ch   = rem & 7;
        const __nv_bfloat16* src = comp ? g_xlo : g_xhi;
        const char* g = (const char*)(src + ((size_t)b * NT + n0 + row) * Cc + kc * 64)
                        + ch * 16;
        CP_ASYNC16(sb + FA_OFF(kc, comp) + swz_v(row, ch), g);
    }
    proj_load_B(sb, 0, 0, 0, tid);
    CP_COMMIT();

    float C[16][4];
    const int r  = lane >> 2;
    const int cq = (lane & 3) * 2;

    #pragma unroll 1
    for (int it = 0; it < 12; it++) {
        const int wi  = it >> 2;
        const int kc  = it & 3;
        const int buf = it & 1;

        if (kc == 0) {
            #pragma unroll
            for (int i = 0; i < 16; i++)
                #pragma unroll
                for (int j = 0; j < 4; j++) C[i][j] = 0.f;
        }

        __syncthreads();
        if (it + 1 < 12) {
            proj_load_B(sb, (it + 1) >> 2, (it + 1) & 3, buf ^ 1, tid);
            CP_COMMIT();
            CP_WAIT1();
        } else {
            CP_WAIT0();
        }
        __syncthreads();

        const uint32_t bh_base = sb + FB_OFF + buf * FB_BUF;
        const uint32_t bl_base = bh_base + 16384;
        const uint32_t ah_base = sb + FA_OFF(kc, 0);
        const uint32_t al_base = sb + FA_OFF(kc, 1);

        #pragma unroll
        for (int kk = 0; kk < 4; kk++) {
            uint32_t ah[4], al[4];
            ldsm_x4(ah_base + swz_v(a_row, 2 * kk + a_c16), ah[0], ah[1], ah[2], ah[3]);
            ldsm_x4(al_base + swz_v(a_row, 2 * kk + a_c16), al[0], al[1], al[2], al[3]);
            #pragma unroll
            for (int nt = 0; nt < 8; nt++) {
                uint32_t bh0, bh1, bh2, bh3, bl0, bl1, bl2, bl3;
                ldsm_x4(bh_base + swz_v(nt * 16 + b_row, 2 * kk + b_ch), bh0, bh1, bh2, bh3);
                ldsm_x4(bl_base + swz_v(nt * 16 + b_row, 2 * kk + b_ch), bl0, bl1, bl2, bl3);
                mma_bf16(C[2 * nt],     ah, bh0, bh1);
                mma_bf16(C[2 * nt + 1], ah, bh2, bh3);
                mma_bf16(C[2 * nt],     ah, bl0, bl1);
                mma_bf16(C[2 * nt + 1], ah, bl2, bl3);
                mma_bf16(C[2 * nt],     al, bh0, bh1);
                mma_bf16(C[2 * nt + 1], al, bh2, bh3);
            }
        }

        if (kc == 3) {
            if (wi < 2) {
                __nv_bfloat16* Bh = (wi == 0) ? g_Qhi : g_Khi;
                __nv_bfloat16* Bl = (wi == 0) ? g_Qlo : g_Klo;
                const float sc = (wi == 0) ? LOG2E : 1.0f;
                #pragma unroll
                for (int nt = 0; nt < 16; nt++) {
                    int d = nt * 8 + cq;
                    __nv_bfloat16 h0, l0, h1, l1;
                    split_bf(C[nt][0] * sc, h0, l0);
                    split_bf(C[nt][1] * sc, h1, l1);
                    size_t o0 = ((size_t)b * NT + n0 + q0 + r) * VC + d;
                    *(uint32_t*)(Bh + o0) = pk(h0, h1);
                    *(uint32_t*)(Bl + o0) = pk(l0, l1);
                    split_bf(C[nt][2] * sc, h0, l0);
                    split_bf(C[nt][3] * sc, h1, l1);
                    size_t o1 = o0 + (size_t)8 * VC;
                    *(uint32_t*)(Bh + o1) = pk(h0, h1);
                    *(uint32_t*)(Bl + o1) = pk(l0, l1);
                }
            } else {
                float* Vt = (float*)psm;   // 64 x 132 floats
                #pragma unroll
                for (int h = 0; h < 2; h++) {
                    __syncthreads();
                    #pragma unroll
                    for (int nt = h * 8; nt < h * 8 + 8; nt++) {
                        int dl = nt * 8 + cq - h * 64;
                        Vt[dl * 132 + q0 + r]           = C[nt][0];
                        Vt[(dl + 1) * 132 + q0 + r]     = C[nt][1];
                        Vt[dl * 132 + q0 + r + 8]       = C[nt][2];
                        Vt[(dl + 1) * 132 + q0 + r + 8] = C[nt][3];
                    }
                    __syncthreads();
                    #pragma unroll
                    for (int i = tid; i < 64 * 64; i += 256) {
                        int dd = i >> 6, n2 = i & 63;
                        __half2 hv = __floats2half2_rn(Vt[dd * 132 + n2 * 2],
                                                       Vt[dd * 132 + n2 * 2 + 1]);
                        *(__half2*)(g_V + ((size_t)b * VC + h * 64 + dd) * NT + n0 + n2 * 2) = hv;
                    }
                }
            }
        }
    }
}

// ---------------------------------------------------------------------------
// Flash attention: bf16 3-pass S + fp16 single-pass PV, online-max (base-2),
// ex2.approx softmax INTERLEAVED with PV mma issue. Proven R7 double-buffer
// pipeline (commit every iteration, wait_group 1).
// smem (160KB): Qhi 0, Qlo 32K, Khi[2] 64K, Klo[2] 96K, V[2] 128K..160K
// ---------------------------------------------------------------------------
#define QHI_OFF 0
#define QLO_OFF 32768
#define KHI_OFF 65536
#define KLO_OFF 98304
#define V_OFF   131072
#define KBUF 16384
#define S_TOTAL 163840

extern __shared__ char fa_sm[];

__device__ __forceinline__ void load_kv(uint32_t sbase, int b, int t, int buf, int tid)
{
    const int k0 = t * BN;
    #pragma unroll
    for (int comp = 0; comp < 2; comp++) {
        const __nv_bfloat16* src = comp ? g_Klo : g_Khi;
        uint32_t dst = sbase + (comp ? KLO_OFF : KHI_OFF) + buf * KBUF;
        #pragma unroll
        for (int i = tid; i < 64 * 16; i += 256) {
            int row = i >> 4, ch = i & 15;
            const char* g = (const char*)(src + ((size_t)b * NT + k0 + row) * VC) + ch * 16;
            CP_ASYNC16(dst + swz_q(row, ch), g);
        }
    }
    {
        uint32_t dst = sbase + V_OFF + buf * KBUF;
        #pragma unroll
        for (int i = tid; i < 128 * 8; i += 256) {
            int row = i >> 3, ch = i & 7;
            const char* g = (const char*)(g_V + ((size_t)b * VC + row) * NT + k0) + ch * 16;
            CP_ASYNC16(dst + swz_v(row, ch), g);
        }
    }
}

__global__ __launch_bounds__(256, 1) void fa_kernel(float* __restrict__ out)
{
    const int tid  = threadIdx.x;
    const int w    = tid >> 5;
    const int lane = tid & 31;
    const int b    = blockIdx.y;
    const int n0   = blockIdx.x * BM;
    const int q0   = w * 16;

    char* sm = fa_sm;
    const uint32_t sbase = smem_u32(sm);

    // stage Q (hi/lo)
    #pragma unroll
    for (int comp = 0; comp < 2; comp++) {
        const __nv_bfloat16* src = comp ? g_Qlo : g_Qhi;
        uint32_t dst = sbase + (comp ? QLO_OFF : QHI_OFF);
        #pragma unroll
        for (int i = tid; i < 128 * 16; i += 256) {
            int row = i >> 4, ch = i & 15;
            const char* g = (const char*)(src + ((size_t)b * NT + n0 + row) * VC) + ch * 16;
            CP_ASYNC16(dst + swz_q(row, ch), g);
        }
    }
    load_kv(sbase, b, 0, 0, tid);
    CP_COMMIT();

    float O[16][4];
    #pragma unroll
    for (int i = 0; i < 16; i++)
        #pragma unroll
        for (int j = 0; j < 4; j++) O[i][j] = 0.f;
    float rs0 = 0.f, rs1 = 0.f;
    float M0 = -1e30f, M1 = -1e30f;

    const int a_row = q0 + (lane & 15);
    const int a_ch  = (lane >> 4);
    const int b_row = (lane & 7) + ((lane >> 4) << 3);
    const int b_ch  = ((lane >> 3) & 1);

    #pragma unroll 1
    for (int t = 0; t < NTILES; t++) {
        const int buf = t & 1;
        if (t + 1 < NTILES) load_kv(sbase, b, t + 1, buf ^ 1, tid);
        CP_COMMIT();
        CP_WAIT1();
        __syncthreads();

        const uint32_t kh_base = sbase + KHI_OFF + buf * KBUF;
        const uint32_t kl_base = sbase + KLO_OFF + buf * KBUF;
        const uint32_t v_base  = sbase + V_OFF   + buf * KBUF;

        // ---- S = Q K^T (bf16 3-pass), base-2 logits (Q pre-scaled) ----
        float C[8][4];
        #pragma unroll
        for (int i = 0; i < 8; i++)
            #pragma unroll
            for (int j = 0; j < 4; j++) C[i][j] = 0.f;

        #pragma unroll
        for (int kc = 0; kc < 8; kc++) {
            uint32_t aqh[4], aql[4];
            ldsm_x4(sbase + QHI_OFF + swz_q(a_row, 2 * kc + a_ch),
                    aqh[0], aqh[1], aqh[2], aqh[3]);
            ldsm_x4(sbase + QLO_OFF + swz_q(a_row, 2 * kc + a_ch),
                    aql[0], aql[1], aql[2], aql[3]);
            #pragma unroll
            for (int ntp = 0; ntp < 4; ntp++) {
                uint32_t bh0, bh1, bh2, bh3, bl0, bl1, bl2, bl3;
                ldsm_x4(kh_base + swz_q(ntp * 16 + b_row, 2 * kc + b_ch),
                        bh0, bh1, bh2, bh3);
                ldsm_x4(kl_base + swz_q(ntp * 16 + b_row, 2 * kc + b_ch),
                        bl0, bl1, bl2, bl3);
                mma_bf16(C[2 * ntp],     aqh, bh0, bh1);
                mma_bf16(C[2 * ntp + 1], aqh, bh2, bh3);
                mma_bf16(C[2 * ntp],     aqh, bl0, bl1);
                mma_bf16(C[2 * ntp + 1], aqh, bl2, bl3);
                mma_bf16(C[2 * ntp],     aql, bh0, bh1);
                mma_bf16(C[2 * ntp + 1], aql, bh2, bh3);
            }
        }

        // ---- row max + rescale ----
        float tm0 = -1e30f, tm1 = -1e30f;
        #pragma unroll
        for (int nt = 0; nt < 8; nt++) {
            tm0 = fmaxf(tm0, fmaxf(C[nt][0], C[nt][1]));
            tm1 = fmaxf(tm1, fmaxf(C[nt][2], C[nt][3]));
        }
        tm0 = fmaxf(tm0, __shfl_xor_sync(0xffffffffu, tm0, 1));
        tm0 = fmaxf(tm0, __shfl_xor_sync(0xffffffffu, tm0, 2));
        tm1 = fmaxf(tm1, __shfl_xor_sync(0xffffffffu, tm1, 1));
        tm1 = fmaxf(tm1, __shfl_xor_sync(0xffffffffu, tm1, 2));
        const float M0n = fmaxf(M0, tm0);
        const float M1n = fmaxf(M1, tm1);
        const float s0 = ex2(M0 - M0n);
        const float s1 = ex2(M1 - M1n);
        M0 = M0n; M1 = M1n;
        rs0 *= s0; rs1 *= s1;

        if (!__all_sync(0xffffffffu, (s0 == 1.0f) & (s1 == 1.0f))) {
            #pragma unroll
            for (int nt = 0; nt < 16; nt++) {
                O[nt][0] *= s0; O[nt][1] *= s0;
                O[nt][2] *= s1; O[nt][3] *= s1;
            }
        }

        // ---- interleaved: per kc group, softmax (exp2/pack) then PV mma ----
        #pragma unroll
        for (int kc = 0; kc < 4; kc++) {
            uint32_t aph[4];
            {
                const int nt = 2 * kc;
                float p0 = ex2(C[nt][0] - M0), p1 = ex2(C[nt][1] - M0);
                float p2 = ex2(C[nt][2] - M1), p3 = ex2(C[nt][3] - M1);
                rs0 += p0 + p1; rs1 += p2 + p3;
                aph[0] = pkh(__float2half_rn(p0), __float2half_rn(p1));
                aph[1] = pkh(__float2half_rn(p2), __float2half_rn(p3));
                p0 = ex2(C[nt + 1][0] - M0); p1 = ex2(C[nt + 1][1] - M0);
                p2 = ex2(C[nt + 1][2] - M1); p3 = ex2(C[nt + 1][3] - M1);
                rs0 += p0 + p1; rs1 += p2 + p3;
                aph[2] = pkh(__float2half_rn(p0), __float2half_rn(p1));
                aph[3] = pkh(__float2half_rn(p2), __float2half_rn(p3));
            }
            #pragma unroll
            for (int ntp = 0; ntp < 8; ntp++) {
                uint32_t v0, v1, v2, v3;
                ldsm_x4(v_base + swz_v(ntp * 16 + b_row, 2 * kc + b_ch),
                        v0, v1, v2, v3);
                mma_f16(O[2 * ntp],     aph, v0, v1);
                mma_f16(O[2 * ntp + 1], aph, v2, v3);
            }
        }
        __syncthreads();   // all warps done with buf before it is refilled
    }

    // ---- finalize ----
    rs0 += __shfl_xor_sync(0xffffffffu, rs0, 1);
    rs0 += __shfl_xor_sync(0xffffffffu, rs0, 2);
    rs1 += __shfl_xor_sync(0xffffffffu, rs1, 1);
    rs1 += __shfl_xor_sync(0xffffffffu, rs1, 2);
    const float inv0 = 1.0f / rs0;
    const float inv1 = 1.0f / rs1;

    __syncthreads();
    float* Ot = (float*)(sm + KHI_OFF);   // 128x132 floats fits in K/V region
    const int r  = lane >> 2;
    const int cc = (lane & 3) * 2;
    #pragma unroll
    for (int nt = 0; nt < 16; nt++) {
        int d = nt * 8 + cc;
        Ot[d * 132 + q0 + r]           = O[nt][0] * inv0;
        Ot[(d + 1) * 132 + q0 + r]     = O[nt][1] * inv0;
        Ot[d * 132 + q0 + r + 8]       = O[nt][2] * inv1;
        Ot[(d + 1) * 132 + q0 + r + 8] = O[nt][3] * inv1;
    }
    __syncthreads();

    float* outb = out + (size_t)b * VC * NT;
    #pragma unroll
    for (int i = tid; i < VC * BM; i += 256) {
        int d = i >> 7, q = i & 127;
        outb[(size_t)d * NT + n0 + q] = Ot[d * 132 + q];
    }
}

// ---------------------------------------------------------------------------
extern "C" void kernel_launch(void* const* d_in, const int* in_sizes, int n_in,
                              void* d_out, int out_size)
{
    const float* x  = (const float*)d_in[0];
    const float* Wq = (const float*)d_in[1];
    const float* Wk = (const float*)d_in[2];
    const float* Wv = (const float*)d_in[3];
    float* out = (float*)d_out;

    wsplit_kernel<<<3 * VC * Cc / 4 / 256, 256>>>(Wq, Wk, Wv);

    dim3 g0(NT / 64, Cc / 64, Bb);
    xsplit_kernel<<<g0, 256>>>(x);

    cudaFuncSetAttribute(proj_fused_kernel, cudaFuncAttributeMaxDynamicSharedMemorySize, PF_SMEM);
    dim3 g1(NT / 128, Bb);
    proj_fused_kernel<<<g1, 256, PF_SMEM>>>();

    cudaFuncSetAttribute(fa_kernel, cudaFuncAttributeMaxDynamicSharedMemorySize, S_TOTAL);
    dim3 g2(NT / BM, Bb);
    fa_kernel<<<g2, 256, S_TOTAL>>>(out);
}